// round 11
// baseline (speedup 1.0000x reference)
#include <cuda_runtime.h>
#include <cuda_fp16.h>
#include <cstdint>
#include <math.h>

#define S_SAMP 32
#define BATCH  1024
#define D_IN   784
#define D_H    1024
#define D_OUT  10
#define K0PAD  832            // 784 padded to multiple of 64

#define NGROUP 4
#define SG     (S_SAMP / NGROUP)   // 8 samples per group

// ---------------------------------------------------------------------------
// Device scratch (static: no cudaMalloc allowed)
// ---------------------------------------------------------------------------
__device__ __half g_x16[(size_t)BATCH * K0PAD];
__device__ __half g_w016[(size_t)S_SAMP * K0PAD * D_H];   // [S][Kpad][N]
__device__ __half g_w116[(size_t)S_SAMP * D_H * D_H];
__device__ __half g_a016[(size_t)S_SAMP * BATCH * D_H];
__device__ __half g_a116[(size_t)S_SAMP * BATCH * D_H];
__device__ float g_sig0[(size_t)D_IN * D_H];
__device__ float g_sig1[(size_t)D_H * D_H];
__device__ float g_b0[S_SAMP * D_H];
__device__ float g_b1[S_SAMP * D_H];
__device__ float g_wl[S_SAMP * D_H * D_OUT];
__device__ float g_bl[S_SAMP * D_OUT];

// ---------------------------------------------------------------------------
// PTX helpers
// ---------------------------------------------------------------------------
__device__ __forceinline__ uint32_t smem_u32(const void* p) {
    uint32_t a;
    asm("{ .reg .u64 t; cvta.to.shared.u64 t, %1; cvt.u32.u64 %0, t; }" : "=r"(a) : "l"(p));
    return a;
}
__device__ __forceinline__ void cp16(uint32_t dst, const void* src) {
    asm volatile("cp.async.cg.shared.global [%0], [%1], 16;" :: "r"(dst), "l"(src) : "memory");
}
#define CP_COMMIT() asm volatile("cp.async.commit_group;" ::: "memory")
#define CP_WAIT(n)  asm volatile("cp.async.wait_group %0;" :: "n"(n) : "memory")

__device__ __forceinline__ void ldsm4(uint32_t* r, uint32_t addr) {
    asm volatile("ldmatrix.sync.aligned.m8n8.x4.shared.b16 {%0,%1,%2,%3}, [%4];"
        : "=r"(r[0]), "=r"(r[1]), "=r"(r[2]), "=r"(r[3]) : "r"(addr));
}
__device__ __forceinline__ void ldsm4t(uint32_t* r, uint32_t addr) {
    asm volatile("ldmatrix.sync.aligned.m8n8.x4.trans.shared.b16 {%0,%1,%2,%3}, [%4];"
        : "=r"(r[0]), "=r"(r[1]), "=r"(r[2]), "=r"(r[3]) : "r"(addr));
}
__device__ __forceinline__ void mma_f16(float* d, const uint32_t* a, const uint32_t* b) {
    asm volatile("mma.sync.aligned.m16n8k16.row.col.f32.f16.f16.f32 "
        "{%0,%1,%2,%3}, {%4,%5,%6,%7}, {%8,%9}, {%0,%1,%2,%3};"
        : "+f"(d[0]), "+f"(d[1]), "+f"(d[2]), "+f"(d[3])
        : "r"(a[0]), "r"(a[1]), "r"(a[2]), "r"(a[3]), "r"(b[0]), "r"(b[1]));
}

// ---------------------------------------------------------------------------
// Prep kernels
// ---------------------------------------------------------------------------
__global__ void prep_sig(const float* __restrict__ wv, float* __restrict__ sig, int n) {
    int i = blockIdx.x * blockDim.x + threadIdx.x;
    if (i < n) sig[i] = expf(0.5f * wv[i]);
}

__global__ void prep_x(const float* __restrict__ x, __half* __restrict__ x16) {
    int i = blockIdx.x * blockDim.x + threadIdx.x;
    if (i >= BATCH * K0PAD) return;
    int b = i / K0PAD, k = i - b * K0PAD;
    float v = (k < D_IN) ? x[b * D_IN + k] : 0.0f;
    x16[i] = __float2half(v);
}

// Streaming sampled weights, [s][Kpad][N], 8 elems/thread; s local to group.
__global__ void __launch_bounds__(256) prep_w(
    const float* __restrict__ we, const float* __restrict__ sig,
    const float* __restrict__ wm, __half* __restrict__ w16,
    int K, int Kpad)
{
    const int s = blockIdx.y;
    const int i = (blockIdx.x * 256 + threadIdx.x) * 8;
    if (i >= Kpad * D_H) return;
    const int k = i >> 10;
    const int n = i & 1023;

    uint4 outv;
    if (k < K) {
        const float* weP = we + ((size_t)s * K + k) * D_H + n;
        const float* sgP = sig + k * D_H + n;
        const float* wmP = wm  + k * D_H + n;
        float4 e0 = *(const float4*)(weP);
        float4 e1 = *(const float4*)(weP + 4);
        float4 s0 = *(const float4*)(sgP);
        float4 s1 = *(const float4*)(sgP + 4);
        float4 m0 = *(const float4*)(wmP);
        float4 m1 = *(const float4*)(wmP + 4);
        __half2 h0 = __floats2half2_rn(fmaf(e0.x, s0.x, m0.x), fmaf(e0.y, s0.y, m0.y));
        __half2 h1 = __floats2half2_rn(fmaf(e0.z, s0.z, m0.z), fmaf(e0.w, s0.w, m0.w));
        __half2 h2 = __floats2half2_rn(fmaf(e1.x, s1.x, m1.x), fmaf(e1.y, s1.y, m1.y));
        __half2 h3 = __floats2half2_rn(fmaf(e1.z, s1.z, m1.z), fmaf(e1.w, s1.w, m1.w));
        outv = make_uint4(*(uint32_t*)&h0, *(uint32_t*)&h1, *(uint32_t*)&h2, *(uint32_t*)&h3);
    } else {
        outv = make_uint4(0, 0, 0, 0);
    }
    *(uint4*)(w16 + (size_t)s * Kpad * D_H + i) = outv;
}

__global__ void prep_sample(const float* __restrict__ e, const float* __restrict__ v,
                            const float* __restrict__ m, float* __restrict__ out,
                            int n, int total) {
    int i = blockIdx.x * blockDim.x + threadIdx.x;
    if (i < total) {
        int j = i % n;
        out[i] = fmaf(e[i], expf(0.5f * v[j]), m[j]);
    }
}

// ---------------------------------------------------------------------------
// HMMA GEMM, fp16 single term, 3-stage cp.async pipeline (s local to group)
// ---------------------------------------------------------------------------
#define GBM 128
#define GBN 128
#define GBK 64
#define NSTAGE 3
#define ROWB_A 144
#define A_MATB (128 * ROWB_A)
#define ROWB_W 272
#define W_MATB (64 * ROWB_W)
#define STAGEB (A_MATB + W_MATB)
#define SMEM_TOTAL (NSTAGE * STAGEB)

__global__ void __launch_bounds__(256, 2) gemm_mma(
    const __half* __restrict__ A16, size_t aStrideS, int Kpad,
    const __half* __restrict__ W16,
    const float* __restrict__ bias,
    __half* __restrict__ Ch)
{
    extern __shared__ __align__(16) char dynsmem[];
    const uint32_t sbase = smem_u32(dynsmem);

    const int tid  = threadIdx.x;
    const int wid  = tid >> 5;
    const int lane = tid & 31;
    const int s  = blockIdx.z;
    const int m0 = blockIdx.y * GBM;
    const int n0 = blockIdx.x * GBN;

    const int warp_m = wid >> 1;
    const int warp_n = wid & 1;

    const __half* aG = A16 + (size_t)s * aStrideS + (size_t)m0 * Kpad;
    const __half* wG = W16 + (size_t)s * Kpad * D_H + n0;

    const int firstHalf = (tid < 128);
    const int lrowA = tid & 127;
    const int wj    = tid & 127;
    const int wrow  = wj >> 1;
    const int wgrp  = wj & 1;

    auto load_chunk = [&](uint32_t st, int k0) {
        if (firstHalf) {
#pragma unroll
            for (int c = 0; c < 8; c++)
                cp16(st + (uint32_t)lrowA * ROWB_A + c * 16,
                     aG + (size_t)lrowA * Kpad + k0 + c * 8);
        } else {
#pragma unroll
            for (int c = 0; c < 8; c++)
                cp16(st + A_MATB + (uint32_t)wrow * ROWB_W + wgrp * 128 + c * 16,
                     wG + (size_t)(k0 + wrow) * D_H + wgrp * 64 + c * 8);
        }
        CP_COMMIT();
    };

    const uint32_t aLaneOff = (uint32_t)(lane & 15) * ROWB_A + (uint32_t)(lane >> 4) * 16
                            + (uint32_t)(warp_m * 32) * ROWB_A;
    const int bm = lane >> 3, br = lane & 7;
    const uint32_t bTransOff = (uint32_t)((bm & 1) * 8 + br) * ROWB_W + (uint32_t)(bm >> 1) * 16
                             + (uint32_t)warp_n * 128;

    float acc[2][8][4];
#pragma unroll
    for (int i = 0; i < 2; i++)
#pragma unroll
        for (int j = 0; j < 8; j++)
#pragma unroll
            for (int q = 0; q < 4; q++) acc[i][j][q] = 0.0f;

    const int nchunks = Kpad / GBK;

    load_chunk(sbase, 0);
    if (nchunks > 1) load_chunk(sbase + STAGEB, GBK);

    int stage = 0;
    for (int it = 0; it < nchunks; it++) {
        if (it + 2 < nchunks) {
            int pst = stage + 2; if (pst >= NSTAGE) pst -= NSTAGE;
            load_chunk(sbase + (uint32_t)pst * STAGEB, (it + 2) * GBK);
            CP_WAIT(2);
        } else if (it + 1 < nchunks) {
            CP_WAIT(1);
        } else {
            CP_WAIT(0);
        }
        __syncthreads();

        const uint32_t st = sbase + (uint32_t)stage * STAGEB;
        const uint32_t aS = st + aLaneOff;
        const uint32_t bS = st + A_MATB + bTransOff;

#pragma unroll
        for (int ks = 0; ks < 4; ks++) {
            uint32_t aa[2][4], bb[16];
#pragma unroll
            for (int mi = 0; mi < 2; mi++)
                ldsm4(aa[mi], aS + mi * 16 * ROWB_A + ks * 32);
#pragma unroll
            for (int p = 0; p < 4; p++)
                ldsm4t(&bb[p * 4], bS + ks * 16 * ROWB_W + p * 32);
#pragma unroll
            for (int mi = 0; mi < 2; mi++)
#pragma unroll
                for (int nj = 0; nj < 8; nj++)
                    mma_f16(acc[mi][nj], aa[mi], &bb[nj * 2]);
        }
        __syncthreads();
        if (++stage >= NSTAGE) stage = 0;
    }

    const int colBase = n0 + warp_n * 64 + (lane & 3) * 2;
    const int rowBase = m0 + warp_m * 32 + (lane >> 2);
    float bias2[8][2];
#pragma unroll
    for (int nj = 0; nj < 8; nj++) {
        const float* bp = bias + (size_t)s * D_H + colBase + nj * 8;
        bias2[nj][0] = bp[0];
        bias2[nj][1] = bp[1];
    }

#pragma unroll
    for (int mi = 0; mi < 2; mi++) {
#pragma unroll
        for (int h = 0; h < 2; h++) {
            const int row = rowBase + mi * 16 + h * 8;
            const size_t rowOff = ((size_t)s * BATCH + row) * D_H;
#pragma unroll
            for (int nj = 0; nj < 8; nj++) {
                float v0 = fmaxf(acc[mi][nj][2 * h]     + bias2[nj][0], 0.0f);
                float v1 = fmaxf(acc[mi][nj][2 * h + 1] + bias2[nj][1], 0.0f);
                __half2 hv = __floats2half2_rn(v0, v1);
                *(__half2*)(Ch + rowOff + colBase + nj * 8) = hv;
            }
        }
    }
}

// ---------------------------------------------------------------------------
// Last layer (s local to group): out[s,b,o] = act16[s,b,:] . wl[s,:,o] + bl[s,o]
// ---------------------------------------------------------------------------
__global__ void __launch_bounds__(256) layer_out(
    const __half* __restrict__ act, const float* __restrict__ wls,
    const float* __restrict__ bls, float* __restrict__ out)
{
    const int s  = blockIdx.y;
    const int m0 = blockIdx.x * 128;

    __shared__ float As[128][33];
    __shared__ float ws[32 * D_OUT];

    const int tid   = threadIdx.x;
    const int crow  = tid >> 1;
    const int obase = (tid & 1) * 5;

    float acc[5] = {0.f, 0.f, 0.f, 0.f, 0.f};
    const int lr = tid >> 2;
    const int lk = (tid & 3) * 8;

    for (int kt = 0; kt < D_H; kt += 32) {
#pragma unroll
        for (int rr = 0; rr < 2; rr++) {
            int r = lr + rr * 64;
            uint4 v = *(const uint4*)(act + ((size_t)s * BATCH + m0 + r) * D_H + kt + lk);
            const __half2* hp = (const __half2*)&v;
#pragma unroll
            for (int q = 0; q < 4; q++) {
                float2 f = __half22float2(hp[q]);
                As[r][lk + 2 * q]     = f.x;
                As[r][lk + 2 * q + 1] = f.y;
            }
        }
        for (int i = tid; i < 32 * D_OUT; i += 256)
            ws[i] = wls[(size_t)s * D_H * D_OUT + kt * D_OUT + i];
        __syncthreads();
#pragma unroll
        for (int k = 0; k < 32; k++) {
            float a = As[crow][k];
#pragma unroll
            for (int j = 0; j < 5; j++)
                acc[j] = fmaf(a, ws[k * D_OUT + obase + j], acc[j]);
        }
        __syncthreads();
    }
#pragma unroll
    for (int j = 0; j < 5; j++)
        out[((size_t)s * BATCH + m0 + crow) * D_OUT + obase + j] = acc[j] + bls[s * D_OUT + obase + j];
}

// ---------------------------------------------------------------------------
// kernel_launch — per-sample-group pipeline (4 groups x 8 samples):
//   stream0 (capture): sig1, x, b0 | G0(0..3) | G1(0..3)          (tensor-bound)
//   strmP:             sig0, b1, wl, bl, w0(0..3), w1(0..3),       (mem-bound,
//                      layer_out(g) after each G1(g)                backfills GEMM waves)
// ---------------------------------------------------------------------------
extern "C" void kernel_launch(void* const* d_in, const int* in_sizes, int n_in,
                              void* d_out, int out_size) {
    const float* x   = (const float*)d_in[0];
    const float* wm0 = (const float*)d_in[1];
    const float* wv0 = (const float*)d_in[2];
    const float* bm0 = (const float*)d_in[3];
    const float* bv0 = (const float*)d_in[4];
    const float* wm1 = (const float*)d_in[5];
    const float* wv1 = (const float*)d_in[6];
    const float* bm1 = (const float*)d_in[7];
    const float* bv1 = (const float*)d_in[8];
    const float* wlm = (const float*)d_in[9];
    const float* wlv = (const float*)d_in[10];
    const float* blm = (const float*)d_in[11];
    const float* blv = (const float*)d_in[12];
    const float* we0 = (const float*)d_in[13];
    const float* be0 = (const float*)d_in[14];
    const float* we1 = (const float*)d_in[15];
    const float* be1 = (const float*)d_in[16];
    const float* wel = (const float*)d_in[17];
    const float* bel = (const float*)d_in[18];
    float* out = (float*)d_out;

    __half *x16, *w016, *w116, *a016, *a116;
    float *sig0, *sig1, *b0, *b1, *wl, *bl;
    cudaGetSymbolAddress((void**)&x16,  g_x16);
    cudaGetSymbolAddress((void**)&w016, g_w016);
    cudaGetSymbolAddress((void**)&w116, g_w116);
    cudaGetSymbolAddress((void**)&a016, g_a016);
    cudaGetSymbolAddress((void**)&a116, g_a116);
    cudaGetSymbolAddress((void**)&sig0, g_sig0);
    cudaGetSymbolAddress((void**)&sig1, g_sig1);
    cudaGetSymbolAddress((void**)&b0,   g_b0);
    cudaGetSymbolAddress((void**)&b1,   g_b1);
    cudaGetSymbolAddress((void**)&wl,   g_wl);
    cudaGetSymbolAddress((void**)&bl,   g_bl);

    static bool init_done = false;
    static cudaStream_t strmP = nullptr;
    static cudaEvent_t evFork, evSig1, evW0[NGROUP], evW1[NGROUP], evG1[NGROUP], evPDone;
    if (!init_done) {
        cudaFuncSetAttribute(gemm_mma, cudaFuncAttributeMaxDynamicSharedMemorySize, SMEM_TOTAL);
        cudaStreamCreateWithFlags(&strmP, cudaStreamNonBlocking);
        cudaEventCreateWithFlags(&evFork,  cudaEventDisableTiming);
        cudaEventCreateWithFlags(&evSig1,  cudaEventDisableTiming);
        cudaEventCreateWithFlags(&evPDone, cudaEventDisableTiming);
        for (int g = 0; g < NGROUP; g++) {
            cudaEventCreateWithFlags(&evW0[g], cudaEventDisableTiming);
            cudaEventCreateWithFlags(&evW1[g], cudaEventDisableTiming);
            cudaEventCreateWithFlags(&evG1[g], cudaEventDisableTiming);
        }
        init_done = true;
    }

    // ---- fork ----
    cudaEventRecord(evFork, 0);
    cudaStreamWaitEvent(strmP, evFork, 0);

    // ---- stream0 head: inputs GEMM0 needs that aren't W0 ----
    {
        int n = D_H * D_H;
        prep_sig<<<(n + 255) / 256, 256>>>(wv1, sig1, n);
        cudaEventRecord(evSig1, 0);
        n = BATCH * K0PAD;
        prep_x<<<(n + 255) / 256, 256>>>(x, x16);
        int total = S_SAMP * D_H;
        prep_sample<<<(total + 255) / 256, 256>>>(be0, bv0, bm0, b0, D_H, total);
    }

    // ---- strmP: sig0, small samples, then W0 groups, then W1 groups ----
    {
        int n = D_IN * D_H;
        prep_sig<<<(n + 255) / 256, 256, 0, strmP>>>(wv0, sig0, n);
        int total = S_SAMP * D_H;
        prep_sample<<<(total + 255) / 256, 256, 0, strmP>>>(be1, bv1, bm1, b1, D_H, total);
        total = S_SAMP * D_H * D_OUT;
        prep_sample<<<(total + 255) / 256, 256, 0, strmP>>>(wel, wlv, wlm, wl, D_H * D_OUT, total);
        total = S_SAMP * D_OUT;
        prep_sample<<<(total + 255) / 256, 256, 0, strmP>>>(bel, blv, blm, bl, D_OUT, total);

        dim3 gw0(K0PAD * D_H / (256 * 8), SG);
        for (int g = 0; g < NGROUP; g++) {
            prep_w<<<gw0, 256, 0, strmP>>>(we0 + (size_t)g * SG * D_IN * D_H, sig0, wm0,
                                           w016 + (size_t)g * SG * K0PAD * D_H, D_IN, K0PAD);
            cudaEventRecord(evW0[g], strmP);
        }
        cudaStreamWaitEvent(strmP, evSig1, 0);
        dim3 gw1(D_H * D_H / (256 * 8), SG);
        for (int g = 0; g < NGROUP; g++) {
            prep_w<<<gw1, 256, 0, strmP>>>(we1 + (size_t)g * SG * D_H * D_H, sig1, wm1,
                                           w116 + (size_t)g * SG * D_H * D_H, D_H, D_H);
            cudaEventRecord(evW1[g], strmP);
        }
    }

    // ---- stream0: GEMM0 groups then GEMM1 groups ----
    {
        dim3 grid(D_H / GBN, BATCH / GBM, SG);
        for (int g = 0; g < NGROUP; g++) {
            cudaStreamWaitEvent(0, evW0[g], 0);
            gemm_mma<<<grid, 256, SMEM_TOTAL>>>(
                x16, 0, K0PAD,
                w016 + (size_t)g * SG * K0PAD * D_H,
                b0 + (size_t)g * SG * D_H,
                a016 + (size_t)g * SG * BATCH * D_H);
        }
        for (int g = 0; g < NGROUP; g++) {
            cudaStreamWaitEvent(0, evW1[g], 0);
            gemm_mma<<<grid, 256, SMEM_TOTAL>>>(
                a016 + (size_t)g * SG * BATCH * D_H, (size_t)BATCH * D_H, D_H,
                w116 + (size_t)g * SG * D_H * D_H,
                b1 + (size_t)g * SG * D_H,
                a116 + (size_t)g * SG * BATCH * D_H);
            cudaEventRecord(evG1[g], 0);
        }
    }

    // ---- strmP: per-group layer_out overlapping later GEMM1 groups ----
    {
        dim3 grid(BATCH / 128, SG);
        for (int g = 0; g < NGROUP; g++) {
            cudaStreamWaitEvent(strmP, evG1[g], 0);
            layer_out<<<grid, 256, 0, strmP>>>(
                a116 + (size_t)g * SG * BATCH * D_H,
                wl + (size_t)g * SG * D_H * D_OUT,
                bl + (size_t)g * SG * D_OUT,
                out + (size_t)g * SG * BATCH * D_OUT);
        }
        cudaEventRecord(evPDone, strmP);
    }

    // ---- join ----
    cudaStreamWaitEvent(0, evPDone, 0);
}

// round 12
// speedup vs baseline: 1.2572x; 1.2572x over previous
#include <cuda_runtime.h>
#include <cuda_fp16.h>
#include <cstdint>
#include <math.h>

#define S_SAMP 32
#define BATCH  1024
#define D_IN   784
#define D_H    1024
#define D_OUT  10
#define K0PAD  832            // 784 padded to multiple of 64

// ---------------------------------------------------------------------------
// Device scratch (static: no cudaMalloc allowed)
// ---------------------------------------------------------------------------
__device__ __half g_x16[(size_t)BATCH * K0PAD];
__device__ __half g_w016[(size_t)S_SAMP * K0PAD * D_H];   // [S][Kpad][N]
__device__ __half g_w116[(size_t)S_SAMP * D_H * D_H];
__device__ __half g_a016[(size_t)S_SAMP * BATCH * D_H];
__device__ __half g_a116[(size_t)S_SAMP * BATCH * D_H];
__device__ float g_sig0[(size_t)D_IN * D_H];
__device__ float g_sig1[(size_t)D_H * D_H];
__device__ float g_b0[S_SAMP * D_H];
__device__ float g_b1[S_SAMP * D_H];
__device__ float g_wl[S_SAMP * D_H * D_OUT];
__device__ float g_bl[S_SAMP * D_OUT];

// ---------------------------------------------------------------------------
// PTX helpers
// ---------------------------------------------------------------------------
__device__ __forceinline__ uint32_t smem_u32(const void* p) {
    uint32_t a;
    asm("{ .reg .u64 t; cvta.to.shared.u64 t, %1; cvt.u32.u64 %0, t; }" : "=r"(a) : "l"(p));
    return a;
}
__device__ __forceinline__ void cp16(uint32_t dst, const void* src) {
    asm volatile("cp.async.cg.shared.global [%0], [%1], 16;" :: "r"(dst), "l"(src) : "memory");
}
#define CP_COMMIT() asm volatile("cp.async.commit_group;" ::: "memory")
#define CP_WAIT(n)  asm volatile("cp.async.wait_group %0;" :: "n"(n) : "memory")

__device__ __forceinline__ void ldsm4(uint32_t* r, uint32_t addr) {
    asm volatile("ldmatrix.sync.aligned.m8n8.x4.shared.b16 {%0,%1,%2,%3}, [%4];"
        : "=r"(r[0]), "=r"(r[1]), "=r"(r[2]), "=r"(r[3]) : "r"(addr));
}
__device__ __forceinline__ void ldsm4t(uint32_t* r, uint32_t addr) {
    asm volatile("ldmatrix.sync.aligned.m8n8.x4.trans.shared.b16 {%0,%1,%2,%3}, [%4];"
        : "=r"(r[0]), "=r"(r[1]), "=r"(r[2]), "=r"(r[3]) : "r"(addr));
}
__device__ __forceinline__ void mma_f16(float* d, const uint32_t* a, const uint32_t* b) {
    asm volatile("mma.sync.aligned.m16n8k16.row.col.f32.f16.f16.f32 "
        "{%0,%1,%2,%3}, {%4,%5,%6,%7}, {%8,%9}, {%0,%1,%2,%3};"
        : "+f"(d[0]), "+f"(d[1]), "+f"(d[2]), "+f"(d[3])
        : "r"(a[0]), "r"(a[1]), "r"(a[2]), "r"(a[3]), "r"(b[0]), "r"(b[1]));
}

// ---------------------------------------------------------------------------
// Prep kernels
// ---------------------------------------------------------------------------
__global__ void prep_sig(const float* __restrict__ wv, float* __restrict__ sig, int n) {
    int i = blockIdx.x * blockDim.x + threadIdx.x;
    if (i < n) sig[i] = expf(0.5f * wv[i]);
}

__global__ void prep_x(const float* __restrict__ x, __half* __restrict__ x16) {
    int i = blockIdx.x * blockDim.x + threadIdx.x;
    if (i >= BATCH * K0PAD) return;
    int b = i / K0PAD, k = i - b * K0PAD;
    float v = (k < D_IN) ? x[b * D_IN + k] : 0.0f;
    x16[i] = __float2half(v);
}

// Streaming sampled weights, [S][Kpad][N], 16 elems/thread (2x uint4 stores):
//   w16[s][k][n] = we[s][k][n] * sig[k][n] + wm[k][n]   (k >= K -> 0)
__global__ void __launch_bounds__(256) prep_w(
    const float* __restrict__ we, const float* __restrict__ sig,
    const float* __restrict__ wm, __half* __restrict__ w16,
    int K, int Kpad)
{
    const int s = blockIdx.y;
    const int i = (blockIdx.x * 256 + threadIdx.x) * 16;
    if (i >= Kpad * D_H) return;
    const int k = i >> 10;
    const int n = i & 1023;

    __half* dst = w16 + (size_t)s * Kpad * D_H + i;
    if (k < K) {
        const float* weP = we + ((size_t)s * K + k) * D_H + n;
        const float* sgP = sig + k * D_H + n;
        const float* wmP = wm  + k * D_H + n;
#pragma unroll
        for (int h = 0; h < 2; h++) {
            float4 e0 = *(const float4*)(weP + h * 8);
            float4 e1 = *(const float4*)(weP + h * 8 + 4);
            float4 s0 = *(const float4*)(sgP + h * 8);
            float4 s1 = *(const float4*)(sgP + h * 8 + 4);
            float4 m0 = *(const float4*)(wmP + h * 8);
            float4 m1 = *(const float4*)(wmP + h * 8 + 4);
            __half2 h0 = __floats2half2_rn(fmaf(e0.x, s0.x, m0.x), fmaf(e0.y, s0.y, m0.y));
            __half2 h1 = __floats2half2_rn(fmaf(e0.z, s0.z, m0.z), fmaf(e0.w, s0.w, m0.w));
            __half2 h2 = __floats2half2_rn(fmaf(e1.x, s1.x, m1.x), fmaf(e1.y, s1.y, m1.y));
            __half2 h3 = __floats2half2_rn(fmaf(e1.z, s1.z, m1.z), fmaf(e1.w, s1.w, m1.w));
            *(uint4*)(dst + h * 8) = make_uint4(*(uint32_t*)&h0, *(uint32_t*)&h1,
                                                *(uint32_t*)&h2, *(uint32_t*)&h3);
        }
    } else {
        *(uint4*)(dst)     = make_uint4(0, 0, 0, 0);
        *(uint4*)(dst + 8) = make_uint4(0, 0, 0, 0);
    }
}

__global__ void prep_sample(const float* __restrict__ e, const float* __restrict__ v,
                            const float* __restrict__ m, float* __restrict__ out,
                            int n, int total) {
    int i = blockIdx.x * blockDim.x + threadIdx.x;
    if (i < total) {
        int j = i % n;
        out[i] = fmaf(e[i], expf(0.5f * v[j]), m[j]);
    }
}

// ---------------------------------------------------------------------------
// HMMA GEMM, fp16 single term, 3-stage cp.async pipeline
// ---------------------------------------------------------------------------
#define GBM 128
#define GBN 128
#define GBK 64
#define NSTAGE 3
#define ROWB_A 144
#define A_MATB (128 * ROWB_A)
#define ROWB_W 272
#define W_MATB (64 * ROWB_W)
#define STAGEB (A_MATB + W_MATB)
#define SMEM_TOTAL (NSTAGE * STAGEB)

__global__ void __launch_bounds__(256, 2) gemm_mma(
    const __half* __restrict__ A16, size_t aStrideS, int Kpad,
    const __half* __restrict__ W16,
    const float* __restrict__ bias,
    __half* __restrict__ Ch)
{
    extern __shared__ __align__(16) char dynsmem[];
    const uint32_t sbase = smem_u32(dynsmem);

    const int tid  = threadIdx.x;
    const int wid  = tid >> 5;
    const int lane = tid & 31;
    const int s  = blockIdx.z;
    const int m0 = blockIdx.y * GBM;
    const int n0 = blockIdx.x * GBN;

    const int warp_m = wid >> 1;
    const int warp_n = wid & 1;

    const __half* aG = A16 + (size_t)s * aStrideS + (size_t)m0 * Kpad;
    const __half* wG = W16 + (size_t)s * Kpad * D_H + n0;

    const int firstHalf = (tid < 128);
    const int lrowA = tid & 127;
    const int wj    = tid & 127;
    const int wrow  = wj >> 1;
    const int wgrp  = wj & 1;

    auto load_chunk = [&](uint32_t st, int k0) {
        if (firstHalf) {
#pragma unroll
            for (int c = 0; c < 8; c++)
                cp16(st + (uint32_t)lrowA * ROWB_A + c * 16,
                     aG + (size_t)lrowA * Kpad + k0 + c * 8);
        } else {
#pragma unroll
            for (int c = 0; c < 8; c++)
                cp16(st + A_MATB + (uint32_t)wrow * ROWB_W + wgrp * 128 + c * 16,
                     wG + (size_t)(k0 + wrow) * D_H + wgrp * 64 + c * 8);
        }
        CP_COMMIT();
    };

    const uint32_t aLaneOff = (uint32_t)(lane & 15) * ROWB_A + (uint32_t)(lane >> 4) * 16
                            + (uint32_t)(warp_m * 32) * ROWB_A;
    const int bm = lane >> 3, br = lane & 7;
    const uint32_t bTransOff = (uint32_t)((bm & 1) * 8 + br) * ROWB_W + (uint32_t)(bm >> 1) * 16
                             + (uint32_t)warp_n * 128;

    float acc[2][8][4];
#pragma unroll
    for (int i = 0; i < 2; i++)
#pragma unroll
        for (int j = 0; j < 8; j++)
#pragma unroll
            for (int q = 0; q < 4; q++) acc[i][j][q] = 0.0f;

    const int nchunks = Kpad / GBK;

    load_chunk(sbase, 0);
    if (nchunks > 1) load_chunk(sbase + STAGEB, GBK);

    int stage = 0;
    for (int it = 0; it < nchunks; it++) {
        if (it + 2 < nchunks) {
            int pst = stage + 2; if (pst >= NSTAGE) pst -= NSTAGE;
            load_chunk(sbase + (uint32_t)pst * STAGEB, (it + 2) * GBK);
            CP_WAIT(2);
        } else if (it + 1 < nchunks) {
            CP_WAIT(1);
        } else {
            CP_WAIT(0);
        }
        __syncthreads();

        const uint32_t st = sbase + (uint32_t)stage * STAGEB;
        const uint32_t aS = st + aLaneOff;
        const uint32_t bS = st + A_MATB + bTransOff;

#pragma unroll
        for (int ks = 0; ks < 4; ks++) {
            uint32_t aa[2][4], bb[16];
#pragma unroll
            for (int mi = 0; mi < 2; mi++)
                ldsm4(aa[mi], aS + mi * 16 * ROWB_A + ks * 32);
#pragma unroll
            for (int p = 0; p < 4; p++)
                ldsm4t(&bb[p * 4], bS + ks * 16 * ROWB_W + p * 32);
#pragma unroll
            for (int mi = 0; mi < 2; mi++)
#pragma unroll
                for (int nj = 0; nj < 8; nj++)
                    mma_f16(acc[mi][nj], aa[mi], &bb[nj * 2]);
        }
        __syncthreads();
        if (++stage >= NSTAGE) stage = 0;
    }

    const int colBase = n0 + warp_n * 64 + (lane & 3) * 2;
    const int rowBase = m0 + warp_m * 32 + (lane >> 2);
    float bias2[8][2];
#pragma unroll
    for (int nj = 0; nj < 8; nj++) {
        const float* bp = bias + (size_t)s * D_H + colBase + nj * 8;
        bias2[nj][0] = bp[0];
        bias2[nj][1] = bp[1];
    }

#pragma unroll
    for (int mi = 0; mi < 2; mi++) {
#pragma unroll
        for (int h = 0; h < 2; h++) {
            const int row = rowBase + mi * 16 + h * 8;
            const size_t rowOff = ((size_t)s * BATCH + row) * D_H;
#pragma unroll
            for (int nj = 0; nj < 8; nj++) {
                float v0 = fmaxf(acc[mi][nj][2 * h]     + bias2[nj][0], 0.0f);
                float v1 = fmaxf(acc[mi][nj][2 * h + 1] + bias2[nj][1], 0.0f);
                __half2 hv = __floats2half2_rn(v0, v1);
                *(__half2*)(Ch + rowOff + colBase + nj * 8) = hv;
            }
        }
    }
}

// ---------------------------------------------------------------------------
// Last layer: out[s,b,o] = act16[s,b,:] . wl[s,:,o] + bl[s,o]
// ---------------------------------------------------------------------------
__global__ void __launch_bounds__(256) layer_out(
    const __half* __restrict__ act, const float* __restrict__ wls,
    const float* __restrict__ bls, float* __restrict__ out)
{
    const int s  = blockIdx.y;
    const int m0 = blockIdx.x * 128;

    __shared__ float As[128][33];
    __shared__ float ws[32 * D_OUT];

    const int tid   = threadIdx.x;
    const int crow  = tid >> 1;
    const int obase = (tid & 1) * 5;

    float acc[5] = {0.f, 0.f, 0.f, 0.f, 0.f};
    const int lr = tid >> 2;
    const int lk = (tid & 3) * 8;

    for (int kt = 0; kt < D_H; kt += 32) {
#pragma unroll
        for (int rr = 0; rr < 2; rr++) {
            int r = lr + rr * 64;
            uint4 v = *(const uint4*)(act + ((size_t)s * BATCH + m0 + r) * D_H + kt + lk);
            const __half2* hp = (const __half2*)&v;
#pragma unroll
            for (int q = 0; q < 4; q++) {
                float2 f = __half22float2(hp[q]);
                As[r][lk + 2 * q]     = f.x;
                As[r][lk + 2 * q + 1] = f.y;
            }
        }
        for (int i = tid; i < 32 * D_OUT; i += 256)
            ws[i] = wls[(size_t)s * D_H * D_OUT + kt * D_OUT + i];
        __syncthreads();
#pragma unroll
        for (int k = 0; k < 32; k++) {
            float a = As[crow][k];
#pragma unroll
            for (int j = 0; j < 5; j++)
                acc[j] = fmaf(a, ws[k * D_OUT + obase + j], acc[j]);
        }
        __syncthreads();
    }
#pragma unroll
    for (int j = 0; j < 5; j++)
        out[((size_t)s * BATCH + m0 + crow) * D_OUT + obase + j] = acc[j] + bls[s * D_OUT + obase + j];
}

// ---------------------------------------------------------------------------
// kernel_launch — R10 structure, but side stream GATED to start after w0 so
// its mem-bound preps run inside GEMM0's tensor-bound window:
//   stream0: sig0, x, b0, w0, [evMain], GEMM0, (wait evP) GEMM1, layer_out
//   strmP:   (wait evMain) sig1, w1, b1, wl, bl, [evP]
// ---------------------------------------------------------------------------
extern "C" void kernel_launch(void* const* d_in, const int* in_sizes, int n_in,
                              void* d_out, int out_size) {
    const float* x   = (const float*)d_in[0];
    const float* wm0 = (const float*)d_in[1];
    const float* wv0 = (const float*)d_in[2];
    const float* bm0 = (const float*)d_in[3];
    const float* bv0 = (const float*)d_in[4];
    const float* wm1 = (const float*)d_in[5];
    const float* wv1 = (const float*)d_in[6];
    const float* bm1 = (const float*)d_in[7];
    const float* bv1 = (const float*)d_in[8];
    const float* wlm = (const float*)d_in[9];
    const float* wlv = (const float*)d_in[10];
    const float* blm = (const float*)d_in[11];
    const float* blv = (const float*)d_in[12];
    const float* we0 = (const float*)d_in[13];
    const float* be0 = (const float*)d_in[14];
    const float* we1 = (const float*)d_in[15];
    const float* be1 = (const float*)d_in[16];
    const float* wel = (const float*)d_in[17];
    const float* bel = (const float*)d_in[18];
    float* out = (float*)d_out;

    __half *x16, *w016, *w116, *a016, *a116;
    float *sig0, *sig1, *b0, *b1, *wl, *bl;
    cudaGetSymbolAddress((void**)&x16,  g_x16);
    cudaGetSymbolAddress((void**)&w016, g_w016);
    cudaGetSymbolAddress((void**)&w116, g_w116);
    cudaGetSymbolAddress((void**)&a016, g_a016);
    cudaGetSymbolAddress((void**)&a116, g_a116);
    cudaGetSymbolAddress((void**)&sig0, g_sig0);
    cudaGetSymbolAddress((void**)&sig1, g_sig1);
    cudaGetSymbolAddress((void**)&b0,   g_b0);
    cudaGetSymbolAddress((void**)&b1,   g_b1);
    cudaGetSymbolAddress((void**)&wl,   g_wl);
    cudaGetSymbolAddress((void**)&bl,   g_bl);

    static bool init_done = false;
    static cudaStream_t strmP = nullptr;
    static cudaEvent_t evMain = nullptr, evP = nullptr;
    if (!init_done) {
        cudaFuncSetAttribute(gemm_mma, cudaFuncAttributeMaxDynamicSharedMemorySize, SMEM_TOTAL);
        cudaStreamCreateWithFlags(&strmP, cudaStreamNonBlocking);
        cudaEventCreateWithFlags(&evMain, cudaEventDisableTiming);
        cudaEventCreateWithFlags(&evP, cudaEventDisableTiming);
        init_done = true;
    }

    // ---- main stream: GEMM0 critical path ----
    {
        int n = D_IN * D_H;
        prep_sig<<<(n + 255) / 256, 256>>>(wv0, sig0, n);
        n = BATCH * K0PAD;
        prep_x<<<(n + 255) / 256, 256>>>(x, x16);
        int total = S_SAMP * D_H;
        prep_sample<<<(total + 255) / 256, 256>>>(be0, bv0, bm0, b0, D_H, total);
        dim3 gw(K0PAD * D_H / (256 * 16), S_SAMP);
        prep_w<<<gw, 256>>>(we0, sig0, wm0, w016, D_IN, K0PAD);
    }

    // ---- fork point: everything after here on strmP overlaps GEMM0 ----
    cudaEventRecord(evMain, 0);
    cudaStreamWaitEvent(strmP, evMain, 0);

    // ---- main: GEMM0 (tensor-bound, ~280 us) ----
    {
        dim3 grid(D_H / GBN, BATCH / GBM, S_SAMP);
        gemm_mma<<<grid, 256, SMEM_TOTAL>>>(x16, 0, K0PAD, w016, b0, a016);
    }

    // ---- side stream: mem-bound preps inside GEMM0's window ----
    {
        int n = D_H * D_H;
        prep_sig<<<(n + 255) / 256, 256, 0, strmP>>>(wv1, sig1, n);
        dim3 gw(D_H * D_H / (256 * 16), S_SAMP);
        prep_w<<<gw, 256, 0, strmP>>>(we1, sig1, wm1, w116, D_H, D_H);
        int total = S_SAMP * D_H;
        prep_sample<<<(total + 255) / 256, 256, 0, strmP>>>(be1, bv1, bm1, b1, D_H, total);
        total = S_SAMP * D_H * D_OUT;
        prep_sample<<<(total + 255) / 256, 256, 0, strmP>>>(wel, wlv, wlm, wl, D_H * D_OUT, total);
        total = S_SAMP * D_OUT;
        prep_sample<<<(total + 255) / 256, 256, 0, strmP>>>(bel, blv, blm, bl, D_OUT, total);
        cudaEventRecord(evP, strmP);
    }

    // ---- join, then layer 1 + output ----
    cudaStreamWaitEvent(0, evP, 0);
    {
        dim3 grid(D_H / GBN, BATCH / GBM, S_SAMP);
        gemm_mma<<<grid, 256, SMEM_TOTAL>>>(a016, (size_t)BATCH * D_H, D_H, w116, b1, a116);
    }
    {
        dim3 grid(BATCH / 128, S_SAMP);
        layer_out<<<grid, 256>>>(a116, wl, bl, out);
    }
}

// round 13
// speedup vs baseline: 1.3633x; 1.0844x over previous
#include <cuda_runtime.h>
#include <cuda_fp16.h>
#include <cstdint>
#include <math.h>

#define S_SAMP 32
#define BATCH  1024
#define D_IN   784
#define D_H    1024
#define D_OUT  10
#define K0PAD  832            // 784 padded to multiple of 64

// ---------------------------------------------------------------------------
// Device scratch (static: no cudaMalloc allowed)
// ---------------------------------------------------------------------------
__device__ __half g_x16[(size_t)BATCH * K0PAD];
__device__ __half g_w016[(size_t)S_SAMP * K0PAD * D_H];   // [S][Kpad][N]
__device__ __half g_w116[(size_t)S_SAMP * D_H * D_H];
__device__ __half g_a016[(size_t)S_SAMP * BATCH * D_H];
__device__ __half g_a116[(size_t)S_SAMP * BATCH * D_H];
__device__ __half g_sig016[(size_t)D_IN * D_H];           // fp16 exp(0.5*wv0)
__device__ __half g_sig116[(size_t)D_H * D_H];
__device__ __half g_wm016[(size_t)D_IN * D_H];            // fp16 wm0
__device__ __half g_wm116[(size_t)D_H * D_H];
__device__ float g_b0[S_SAMP * D_H];
__device__ float g_b1[S_SAMP * D_H];
__device__ float g_wl[S_SAMP * D_H * D_OUT];
__device__ float g_bl[S_SAMP * D_OUT];

// ---------------------------------------------------------------------------
// PTX helpers
// ---------------------------------------------------------------------------
__device__ __forceinline__ uint32_t smem_u32(const void* p) {
    uint32_t a;
    asm("{ .reg .u64 t; cvta.to.shared.u64 t, %1; cvt.u32.u64 %0, t; }" : "=r"(a) : "l"(p));
    return a;
}
__device__ __forceinline__ void cp16(uint32_t dst, const void* src) {
    asm volatile("cp.async.cg.shared.global [%0], [%1], 16;" :: "r"(dst), "l"(src) : "memory");
}
#define CP_COMMIT() asm volatile("cp.async.commit_group;" ::: "memory")
#define CP_WAIT(n)  asm volatile("cp.async.wait_group %0;" :: "n"(n) : "memory")

__device__ __forceinline__ void ldsm4(uint32_t* r, uint32_t addr) {
    asm volatile("ldmatrix.sync.aligned.m8n8.x4.shared.b16 {%0,%1,%2,%3}, [%4];"
        : "=r"(r[0]), "=r"(r[1]), "=r"(r[2]), "=r"(r[3]) : "r"(addr));
}
__device__ __forceinline__ void ldsm4t(uint32_t* r, uint32_t addr) {
    asm volatile("ldmatrix.sync.aligned.m8n8.x4.trans.shared.b16 {%0,%1,%2,%3}, [%4];"
        : "=r"(r[0]), "=r"(r[1]), "=r"(r[2]), "=r"(r[3]) : "r"(addr));
}
__device__ __forceinline__ void mma_f16(float* d, const uint32_t* a, const uint32_t* b) {
    asm volatile("mma.sync.aligned.m16n8k16.row.col.f32.f16.f16.f32 "
        "{%0,%1,%2,%3}, {%4,%5,%6,%7}, {%8,%9}, {%0,%1,%2,%3};"
        : "+f"(d[0]), "+f"(d[1]), "+f"(d[2]), "+f"(d[3])
        : "r"(a[0]), "r"(a[1]), "r"(a[2]), "r"(a[3]), "r"(b[0]), "r"(b[1]));
}

// ---------------------------------------------------------------------------
// Prep kernels
// ---------------------------------------------------------------------------
__global__ void prep_sig16(const float* __restrict__ wv, __half* __restrict__ sig, int n) {
    int i = blockIdx.x * blockDim.x + threadIdx.x;
    if (i < n) sig[i] = __float2half(expf(0.5f * wv[i]));
}

__global__ void prep_f2h(const float* __restrict__ src, __half* __restrict__ dst, int n) {
    int i = blockIdx.x * blockDim.x + threadIdx.x;
    if (i < n) dst[i] = __float2half(src[i]);
}

__global__ void prep_x(const float* __restrict__ x, __half* __restrict__ x16) {
    int i = blockIdx.x * blockDim.x + threadIdx.x;
    if (i >= BATCH * K0PAD) return;
    int b = i / K0PAD, k = i - b * K0PAD;
    float v = (k < D_IN) ? x[b * D_IN + k] : 0.0f;
    x16[i] = __float2half(v);
}

// Streaming sampled weights, [S][Kpad][N], 8 elems/thread, fp16 sig/wm planes:
//   w16[s][k][n] = we[s][k][n] * sig16[k][n] + wm16[k][n]   (k >= K -> 0)
__global__ void __launch_bounds__(256) prep_w(
    const float* __restrict__ we, const __half* __restrict__ sig,
    const __half* __restrict__ wm, __half* __restrict__ w16,
    int K, int Kpad)
{
    const int s = blockIdx.y;
    const int i = (blockIdx.x * 256 + threadIdx.x) * 8;
    if (i >= Kpad * D_H) return;
    const int k = i >> 10;
    const int n = i & 1023;

    uint4 outv;
    if (k < K) {
        const float* weP  = we + ((size_t)s * K + k) * D_H + n;
        float4 e0 = *(const float4*)(weP);
        float4 e1 = *(const float4*)(weP + 4);
        uint4 sgv = *(const uint4*)(sig + k * D_H + n);
        uint4 mmv = *(const uint4*)(wm  + k * D_H + n);
        const __half2* sgh = (const __half2*)&sgv;
        const __half2* mmh = (const __half2*)&mmv;
        float2 s0 = __half22float2(sgh[0]), s1 = __half22float2(sgh[1]);
        float2 s2 = __half22float2(sgh[2]), s3 = __half22float2(sgh[3]);
        float2 m0 = __half22float2(mmh[0]), m1 = __half22float2(mmh[1]);
        float2 m2 = __half22float2(mmh[2]), m3 = __half22float2(mmh[3]);
        __half2 h0 = __floats2half2_rn(fmaf(e0.x, s0.x, m0.x), fmaf(e0.y, s0.y, m0.y));
        __half2 h1 = __floats2half2_rn(fmaf(e0.z, s1.x, m1.x), fmaf(e0.w, s1.y, m1.y));
        __half2 h2 = __floats2half2_rn(fmaf(e1.x, s2.x, m2.x), fmaf(e1.y, s2.y, m2.y));
        __half2 h3 = __floats2half2_rn(fmaf(e1.z, s3.x, m3.x), fmaf(e1.w, s3.y, m3.y));
        outv = make_uint4(*(uint32_t*)&h0, *(uint32_t*)&h1, *(uint32_t*)&h2, *(uint32_t*)&h3);
    } else {
        outv = make_uint4(0, 0, 0, 0);
    }
    *(uint4*)(w16 + (size_t)s * Kpad * D_H + i) = outv;
}

__global__ void prep_sample(const float* __restrict__ e, const float* __restrict__ v,
                            const float* __restrict__ m, float* __restrict__ out,
                            int n, int total) {
    int i = blockIdx.x * blockDim.x + threadIdx.x;
    if (i < total) {
        int j = i % n;
        out[i] = fmaf(e[i], expf(0.5f * v[j]), m[j]);
    }
}

// ---------------------------------------------------------------------------
// HMMA GEMM, fp16 single term, 3-stage cp.async pipeline (unchanged from R10)
// ---------------------------------------------------------------------------
#define GBM 128
#define GBN 128
#define GBK 64
#define NSTAGE 3
#define ROWB_A 144
#define A_MATB (128 * ROWB_A)
#define ROWB_W 272
#define W_MATB (64 * ROWB_W)
#define STAGEB (A_MATB + W_MATB)
#define SMEM_TOTAL (NSTAGE * STAGEB)

__global__ void __launch_bounds__(256, 2) gemm_mma(
    const __half* __restrict__ A16, size_t aStrideS, int Kpad,
    const __half* __restrict__ W16,
    const float* __restrict__ bias,
    __half* __restrict__ Ch)
{
    extern __shared__ __align__(16) char dynsmem[];
    const uint32_t sbase = smem_u32(dynsmem);

    const int tid  = threadIdx.x;
    const int wid  = tid >> 5;
    const int lane = tid & 31;
    const int s  = blockIdx.z;
    const int m0 = blockIdx.y * GBM;
    const int n0 = blockIdx.x * GBN;

    const int warp_m = wid >> 1;
    const int warp_n = wid & 1;

    const __half* aG = A16 + (size_t)s * aStrideS + (size_t)m0 * Kpad;
    const __half* wG = W16 + (size_t)s * Kpad * D_H + n0;

    const int firstHalf = (tid < 128);
    const int lrowA = tid & 127;
    const int wj    = tid & 127;
    const int wrow  = wj >> 1;
    const int wgrp  = wj & 1;

    auto load_chunk = [&](uint32_t st, int k0) {
        if (firstHalf) {
#pragma unroll
            for (int c = 0; c < 8; c++)
                cp16(st + (uint32_t)lrowA * ROWB_A + c * 16,
                     aG + (size_t)lrowA * Kpad + k0 + c * 8);
        } else {
#pragma unroll
            for (int c = 0; c < 8; c++)
                cp16(st + A_MATB + (uint32_t)wrow * ROWB_W + wgrp * 128 + c * 16,
                     wG + (size_t)(k0 + wrow) * D_H + wgrp * 64 + c * 8);
        }
        CP_COMMIT();
    };

    const uint32_t aLaneOff = (uint32_t)(lane & 15) * ROWB_A + (uint32_t)(lane >> 4) * 16
                            + (uint32_t)(warp_m * 32) * ROWB_A;
    const int bm = lane >> 3, br = lane & 7;
    const uint32_t bTransOff = (uint32_t)((bm & 1) * 8 + br) * ROWB_W + (uint32_t)(bm >> 1) * 16
                             + (uint32_t)warp_n * 128;

    float acc[2][8][4];
#pragma unroll
    for (int i = 0; i < 2; i++)
#pragma unroll
        for (int j = 0; j < 8; j++)
#pragma unroll
            for (int q = 0; q < 4; q++) acc[i][j][q] = 0.0f;

    const int nchunks = Kpad / GBK;

    load_chunk(sbase, 0);
    if (nchunks > 1) load_chunk(sbase + STAGEB, GBK);

    int stage = 0;
    for (int it = 0; it < nchunks; it++) {
        if (it + 2 < nchunks) {
            int pst = stage + 2; if (pst >= NSTAGE) pst -= NSTAGE;
            load_chunk(sbase + (uint32_t)pst * STAGEB, (it + 2) * GBK);
            CP_WAIT(2);
        } else if (it + 1 < nchunks) {
            CP_WAIT(1);
        } else {
            CP_WAIT(0);
        }
        __syncthreads();

        const uint32_t st = sbase + (uint32_t)stage * STAGEB;
        const uint32_t aS = st + aLaneOff;
        const uint32_t bS = st + A_MATB + bTransOff;

#pragma unroll
        for (int ks = 0; ks < 4; ks++) {
            uint32_t aa[2][4], bb[16];
#pragma unroll
            for (int mi = 0; mi < 2; mi++)
                ldsm4(aa[mi], aS + mi * 16 * ROWB_A + ks * 32);
#pragma unroll
            for (int p = 0; p < 4; p++)
                ldsm4t(&bb[p * 4], bS + ks * 16 * ROWB_W + p * 32);
#pragma unroll
            for (int mi = 0; mi < 2; mi++)
#pragma unroll
                for (int nj = 0; nj < 8; nj++)
                    mma_f16(acc[mi][nj], aa[mi], &bb[nj * 2]);
        }
        __syncthreads();
        if (++stage >= NSTAGE) stage = 0;
    }

    const int colBase = n0 + warp_n * 64 + (lane & 3) * 2;
    const int rowBase = m0 + warp_m * 32 + (lane >> 2);
    float bias2[8][2];
#pragma unroll
    for (int nj = 0; nj < 8; nj++) {
        const float* bp = bias + (size_t)s * D_H + colBase + nj * 8;
        bias2[nj][0] = bp[0];
        bias2[nj][1] = bp[1];
    }

#pragma unroll
    for (int mi = 0; mi < 2; mi++) {
#pragma unroll
        for (int h = 0; h < 2; h++) {
            const int row = rowBase + mi * 16 + h * 8;
            const size_t rowOff = ((size_t)s * BATCH + row) * D_H;
#pragma unroll
            for (int nj = 0; nj < 8; nj++) {
                float v0 = fmaxf(acc[mi][nj][2 * h]     + bias2[nj][0], 0.0f);
                float v1 = fmaxf(acc[mi][nj][2 * h + 1] + bias2[nj][1], 0.0f);
                __half2 hv = __floats2half2_rn(v0, v1);
                *(__half2*)(Ch + rowOff + colBase + nj * 8) = hv;
            }
        }
    }
}

// ---------------------------------------------------------------------------
// Last layer: out[s,b,o] = act16[s,b,:] . wl[s,:,o] + bl[s,o]
// ---------------------------------------------------------------------------
__global__ void __launch_bounds__(256) layer_out(
    const __half* __restrict__ act, const float* __restrict__ wls,
    const float* __restrict__ bls, float* __restrict__ out)
{
    const int s  = blockIdx.y;
    const int m0 = blockIdx.x * 128;

    __shared__ float As[128][33];
    __shared__ float ws[32 * D_OUT];

    const int tid   = threadIdx.x;
    const int crow  = tid >> 1;
    const int obase = (tid & 1) * 5;

    float acc[5] = {0.f, 0.f, 0.f, 0.f, 0.f};
    const int lr = tid >> 2;
    const int lk = (tid & 3) * 8;

    for (int kt = 0; kt < D_H; kt += 32) {
#pragma unroll
        for (int rr = 0; rr < 2; rr++) {
            int r = lr + rr * 64;
            uint4 v = *(const uint4*)(act + ((size_t)s * BATCH + m0 + r) * D_H + kt + lk);
            const __half2* hp = (const __half2*)&v;
#pragma unroll
            for (int q = 0; q < 4; q++) {
                float2 f = __half22float2(hp[q]);
                As[r][lk + 2 * q]     = f.x;
                As[r][lk + 2 * q + 1] = f.y;
            }
        }
        for (int i = tid; i < 32 * D_OUT; i += 256)
            ws[i] = wls[(size_t)s * D_H * D_OUT + kt * D_OUT + i];
        __syncthreads();
#pragma unroll
        for (int k = 0; k < 32; k++) {
            float a = As[crow][k];
#pragma unroll
            for (int j = 0; j < 5; j++)
                acc[j] = fmaf(a, ws[k * D_OUT + obase + j], acc[j]);
        }
        __syncthreads();
    }
#pragma unroll
    for (int j = 0; j < 5; j++)
        out[((size_t)s * BATCH + m0 + crow) * D_OUT + obase + j] = acc[j] + bls[s * D_OUT + obase + j];
}

// ---------------------------------------------------------------------------
// kernel_launch — R10 structure (best known): plain fork, side stream runs
// layer-1/last-layer preps concurrently with main-stream preps + GEMM0.
// ---------------------------------------------------------------------------
extern "C" void kernel_launch(void* const* d_in, const int* in_sizes, int n_in,
                              void* d_out, int out_size) {
    const float* x   = (const float*)d_in[0];
    const float* wm0 = (const float*)d_in[1];
    const float* wv0 = (const float*)d_in[2];
    const float* bm0 = (const float*)d_in[3];
    const float* bv0 = (const float*)d_in[4];
    const float* wm1 = (const float*)d_in[5];
    const float* wv1 = (const float*)d_in[6];
    const float* bm1 = (const float*)d_in[7];
    const float* bv1 = (const float*)d_in[8];
    const float* wlm = (const float*)d_in[9];
    const float* wlv = (const float*)d_in[10];
    const float* blm = (const float*)d_in[11];
    const float* blv = (const float*)d_in[12];
    const float* we0 = (const float*)d_in[13];
    const float* be0 = (const float*)d_in[14];
    const float* we1 = (const float*)d_in[15];
    const float* be1 = (const float*)d_in[16];
    const float* wel = (const float*)d_in[17];
    const float* bel = (const float*)d_in[18];
    float* out = (float*)d_out;

    __half *x16, *w016, *w116, *a016, *a116, *sig016, *sig116, *wm016, *wm116;
    float *b0, *b1, *wl, *bl;
    cudaGetSymbolAddress((void**)&x16,    g_x16);
    cudaGetSymbolAddress((void**)&w016,   g_w016);
    cudaGetSymbolAddress((void**)&w116,   g_w116);
    cudaGetSymbolAddress((void**)&a016,   g_a016);
    cudaGetSymbolAddress((void**)&a116,   g_a116);
    cudaGetSymbolAddress((void**)&sig016, g_sig016);
    cudaGetSymbolAddress((void**)&sig116, g_sig116);
    cudaGetSymbolAddress((void**)&wm016,  g_wm016);
    cudaGetSymbolAddress((void**)&wm116,  g_wm116);
    cudaGetSymbolAddress((void**)&b0,     g_b0);
    cudaGetSymbolAddress((void**)&b1,     g_b1);
    cudaGetSymbolAddress((void**)&wl,     g_wl);
    cudaGetSymbolAddress((void**)&bl,     g_bl);

    static bool init_done = false;
    static cudaStream_t strm2 = nullptr;
    static cudaEvent_t evFork = nullptr, evJoin = nullptr;
    if (!init_done) {
        cudaFuncSetAttribute(gemm_mma, cudaFuncAttributeMaxDynamicSharedMemorySize, SMEM_TOTAL);
        cudaStreamCreateWithFlags(&strm2, cudaStreamNonBlocking);
        cudaEventCreateWithFlags(&evFork, cudaEventDisableTiming);
        cudaEventCreateWithFlags(&evJoin, cudaEventDisableTiming);
        init_done = true;
    }

    // ---- fork ----
    cudaEventRecord(evFork, 0);
    cudaStreamWaitEvent(strm2, evFork, 0);

    // ---- side stream: everything GEMM0 does NOT need ----
    {
        int n = D_H * D_H;
        prep_sig16<<<(n + 255) / 256, 256, 0, strm2>>>(wv1, sig116, n);
        prep_f2h<<<(n + 255) / 256, 256, 0, strm2>>>(wm1, wm116, n);
        dim3 grid(D_H * D_H / (256 * 8), S_SAMP);
        prep_w<<<grid, 256, 0, strm2>>>(we1, sig116, wm116, w116, D_H, D_H);
        int total = S_SAMP * D_H;
        prep_sample<<<(total + 255) / 256, 256, 0, strm2>>>(be1, bv1, bm1, b1, D_H, total);
        total = S_SAMP * D_H * D_OUT;
        prep_sample<<<(total + 255) / 256, 256, 0, strm2>>>(wel, wlv, wlm, wl, D_H * D_OUT, total);
        total = S_SAMP * D_OUT;
        prep_sample<<<(total + 255) / 256, 256, 0, strm2>>>(bel, blv, blm, bl, D_OUT, total);
        cudaEventRecord(evJoin, strm2);
    }

    // ---- main stream: GEMM0 critical path ----
    {
        int n = D_IN * D_H;
        prep_sig16<<<(n + 255) / 256, 256>>>(wv0, sig016, n);
        prep_f2h<<<(n + 255) / 256, 256>>>(wm0, wm016, n);
        n = BATCH * K0PAD;
        prep_x<<<(n + 255) / 256, 256>>>(x, x16);
        int total = S_SAMP * D_H;
        prep_sample<<<(total + 255) / 256, 256>>>(be0, bv0, bm0, b0, D_H, total);
        dim3 gw(K0PAD * D_H / (256 * 8), S_SAMP);
        prep_w<<<gw, 256>>>(we0, sig016, wm016, w016, D_IN, K0PAD);
        dim3 grid(D_H / GBN, BATCH / GBM, S_SAMP);
        gemm_mma<<<grid, 256, SMEM_TOTAL>>>(x16, 0, K0PAD, w016, b0, a016);
    }

    // ---- join, then layer 1 + output ----
    cudaStreamWaitEvent(0, evJoin, 0);
    {
        dim3 grid(D_H / GBN, BATCH / GBM, S_SAMP);
        gemm_mma<<<grid, 256, SMEM_TOTAL>>>(a016, (size_t)BATCH * D_H, D_H, w116, b1, a116);
    }
    {
        dim3 grid(BATCH / 128, S_SAMP);
        layer_out<<<grid, 256>>>(a116, wl, bl, out);
    }
}

// round 14
// speedup vs baseline: 1.3910x; 1.0203x over previous
#include <cuda_runtime.h>
#include <cuda_fp16.h>
#include <cstdint>
#include <math.h>

#define S_SAMP 32
#define BATCH  1024
#define D_IN   784
#define D_H    1024
#define D_OUT  10
#define K0PAD  832            // 784 padded to multiple of 64

// ---------------------------------------------------------------------------
// Device scratch (static: no cudaMalloc allowed)
// ---------------------------------------------------------------------------
__device__ __half g_x16[(size_t)BATCH * K0PAD];
__device__ __half g_w016[(size_t)S_SAMP * K0PAD * D_H];   // [S][Kpad][N]
__device__ __half g_w116[(size_t)S_SAMP * D_H * D_H];
__device__ __half g_a016[(size_t)S_SAMP * BATCH * D_H];
__device__ __half g_a116[(size_t)S_SAMP * BATCH * D_H];
__device__ __half g_sig016[(size_t)D_IN * D_H];           // fp16 exp(0.5*wv0)
__device__ __half g_sig116[(size_t)D_H * D_H];
__device__ __half g_wm016[(size_t)D_IN * D_H];            // fp16 wm0
__device__ __half g_wm116[(size_t)D_H * D_H];
__device__ float g_b0[S_SAMP * D_H];
__device__ float g_b1[S_SAMP * D_H];
__device__ float g_wl[S_SAMP * D_H * D_OUT];
__device__ float g_bl[S_SAMP * D_OUT];

// ---------------------------------------------------------------------------
// PTX helpers
// ---------------------------------------------------------------------------
__device__ __forceinline__ uint32_t smem_u32(const void* p) {
    uint32_t a;
    asm("{ .reg .u64 t; cvta.to.shared.u64 t, %1; cvt.u32.u64 %0, t; }" : "=r"(a) : "l"(p));
    return a;
}
__device__ __forceinline__ void cp16(uint32_t dst, const void* src) {
    asm volatile("cp.async.cg.shared.global [%0], [%1], 16;" :: "r"(dst), "l"(src) : "memory");
}
#define CP_COMMIT() asm volatile("cp.async.commit_group;" ::: "memory")
#define CP_WAIT(n)  asm volatile("cp.async.wait_group %0;" :: "n"(n) : "memory")

__device__ __forceinline__ void ldsm4(uint32_t* r, uint32_t addr) {
    asm volatile("ldmatrix.sync.aligned.m8n8.x4.shared.b16 {%0,%1,%2,%3}, [%4];"
        : "=r"(r[0]), "=r"(r[1]), "=r"(r[2]), "=r"(r[3]) : "r"(addr));
}
__device__ __forceinline__ void ldsm4t(uint32_t* r, uint32_t addr) {
    asm volatile("ldmatrix.sync.aligned.m8n8.x4.trans.shared.b16 {%0,%1,%2,%3}, [%4];"
        : "=r"(r[0]), "=r"(r[1]), "=r"(r[2]), "=r"(r[3]) : "r"(addr));
}
__device__ __forceinline__ void mma_f16(float* d, const uint32_t* a, const uint32_t* b) {
    asm volatile("mma.sync.aligned.m16n8k16.row.col.f32.f16.f16.f32 "
        "{%0,%1,%2,%3}, {%4,%5,%6,%7}, {%8,%9}, {%0,%1,%2,%3};"
        : "+f"(d[0]), "+f"(d[1]), "+f"(d[2]), "+f"(d[3])
        : "r"(a[0]), "r"(a[1]), "r"(a[2]), "r"(a[3]), "r"(b[0]), "r"(b[1]));
}

// ---------------------------------------------------------------------------
// Prep kernels
// ---------------------------------------------------------------------------
__global__ void prep_sig16(const float* __restrict__ wv, __half* __restrict__ sig, int n) {
    int i = blockIdx.x * blockDim.x + threadIdx.x;
    if (i < n) sig[i] = __float2half(expf(0.5f * wv[i]));
}

__global__ void prep_f2h(const float* __restrict__ src, __half* __restrict__ dst, int n) {
    int i = blockIdx.x * blockDim.x + threadIdx.x;
    if (i < n) dst[i] = __float2half(src[i]);
}

__global__ void prep_x(const float* __restrict__ x, __half* __restrict__ x16) {
    int i = blockIdx.x * blockDim.x + threadIdx.x;
    if (i >= BATCH * K0PAD) return;
    int b = i / K0PAD, k = i - b * K0PAD;
    float v = (k < D_IN) ? x[b * D_IN + k] : 0.0f;
    x16[i] = __float2half(v);
}

// Streaming sampled weights, [S][Kpad][N], 8 elems/thread, fp16 sig/wm planes:
//   w16[s][k][n] = we[s][k][n] * sig16[k][n] + wm16[k][n]   (k >= K -> 0)
__global__ void __launch_bounds__(256) prep_w(
    const float* __restrict__ we, const __half* __restrict__ sig,
    const __half* __restrict__ wm, __half* __restrict__ w16,
    int K, int Kpad)
{
    const int s = blockIdx.y;
    const int i = (blockIdx.x * 256 + threadIdx.x) * 8;
    if (i >= Kpad * D_H) return;
    const int k = i >> 10;
    const int n = i & 1023;

    uint4 outv;
    if (k < K) {
        const float* weP  = we + ((size_t)s * K + k) * D_H + n;
        float4 e0 = *(const float4*)(weP);
        float4 e1 = *(const float4*)(weP + 4);
        uint4 sgv = *(const uint4*)(sig + k * D_H + n);
        uint4 mmv = *(const uint4*)(wm  + k * D_H + n);
        const __half2* sgh = (const __half2*)&sgv;
        const __half2* mmh = (const __half2*)&mmv;
        float2 s0 = __half22float2(sgh[0]), s1 = __half22float2(sgh[1]);
        float2 s2 = __half22float2(sgh[2]), s3 = __half22float2(sgh[3]);
        float2 m0 = __half22float2(mmh[0]), m1 = __half22float2(mmh[1]);
        float2 m2 = __half22float2(mmh[2]), m3 = __half22float2(mmh[3]);
        __half2 h0 = __floats2half2_rn(fmaf(e0.x, s0.x, m0.x), fmaf(e0.y, s0.y, m0.y));
        __half2 h1 = __floats2half2_rn(fmaf(e0.z, s1.x, m1.x), fmaf(e0.w, s1.y, m1.y));
        __half2 h2 = __floats2half2_rn(fmaf(e1.x, s2.x, m2.x), fmaf(e1.y, s2.y, m2.y));
        __half2 h3 = __floats2half2_rn(fmaf(e1.z, s3.x, m3.x), fmaf(e1.w, s3.y, m3.y));
        outv = make_uint4(*(uint32_t*)&h0, *(uint32_t*)&h1, *(uint32_t*)&h2, *(uint32_t*)&h3);
    } else {
        outv = make_uint4(0, 0, 0, 0);
    }
    *(uint4*)(w16 + (size_t)s * Kpad * D_H + i) = outv;
}

__global__ void prep_sample(const float* __restrict__ e, const float* __restrict__ v,
                            const float* __restrict__ m, float* __restrict__ out,
                            int n, int total) {
    int i = blockIdx.x * blockDim.x + threadIdx.x;
    if (i < total) {
        int j = i % n;
        out[i] = fmaf(e[i], expf(0.5f * v[j]), m[j]);
    }
}

// ---------------------------------------------------------------------------
// HMMA GEMM, fp16 single term, 3-stage cp.async pipeline, SINGLE barrier/chunk:
//   loop: CP_WAIT(1) -> sync -> prefetch(it+2) -> compute(it)
//   (barrier at iter it proves all warps finished compute it-1, so writing
//    stage (it+2)%3 == (it-1)%3 after it is race-free)
// ---------------------------------------------------------------------------
#define GBM 128
#define GBN 128
#define GBK 64
#define NSTAGE 3
#define ROWB_A 144
#define A_MATB (128 * ROWB_A)
#define ROWB_W 272
#define W_MATB (64 * ROWB_W)
#define STAGEB (A_MATB + W_MATB)
#define SMEM_TOTAL (NSTAGE * STAGEB)

__global__ void __launch_bounds__(256, 2) gemm_mma(
    const __half* __restrict__ A16, size_t aStrideS, int Kpad,
    const __half* __restrict__ W16,
    const float* __restrict__ bias,
    __half* __restrict__ Ch)
{
    extern __shared__ __align__(16) char dynsmem[];
    const uint32_t sbase = smem_u32(dynsmem);

    const int tid  = threadIdx.x;
    const int wid  = tid >> 5;
    const int lane = tid & 31;
    const int s  = blockIdx.z;
    const int m0 = blockIdx.y * GBM;
    const int n0 = blockIdx.x * GBN;

    const int warp_m = wid >> 1;
    const int warp_n = wid & 1;

    const __half* aG = A16 + (size_t)s * aStrideS + (size_t)m0 * Kpad;
    const __half* wG = W16 + (size_t)s * Kpad * D_H + n0;

    const int firstHalf = (tid < 128);
    const int lrowA = tid & 127;
    const int wj    = tid & 127;
    const int wrow  = wj >> 1;
    const int wgrp  = wj & 1;

    auto load_chunk = [&](uint32_t st, int k0) {
        if (firstHalf) {
#pragma unroll
            for (int c = 0; c < 8; c++)
                cp16(st + (uint32_t)lrowA * ROWB_A + c * 16,
                     aG + (size_t)lrowA * Kpad + k0 + c * 8);
        } else {
#pragma unroll
            for (int c = 0; c < 8; c++)
                cp16(st + A_MATB + (uint32_t)wrow * ROWB_W + wgrp * 128 + c * 16,
                     wG + (size_t)(k0 + wrow) * D_H + wgrp * 64 + c * 8);
        }
        CP_COMMIT();
    };

    const uint32_t aLaneOff = (uint32_t)(lane & 15) * ROWB_A + (uint32_t)(lane >> 4) * 16
                            + (uint32_t)(warp_m * 32) * ROWB_A;
    const int bm = lane >> 3, br = lane & 7;
    const uint32_t bTransOff = (uint32_t)((bm & 1) * 8 + br) * ROWB_W + (uint32_t)(bm >> 1) * 16
                             + (uint32_t)warp_n * 128;

    float acc[2][8][4];
#pragma unroll
    for (int i = 0; i < 2; i++)
#pragma unroll
        for (int j = 0; j < 8; j++)
#pragma unroll
            for (int q = 0; q < 4; q++) acc[i][j][q] = 0.0f;

    const int nchunks = Kpad / GBK;

    // prologue: chunks 0,1 in flight
    load_chunk(sbase, 0);
    if (nchunks > 1) load_chunk(sbase + STAGEB, GBK);

    int stage = 0;
    for (int it = 0; it < nchunks; it++) {
        if (it + 1 < nchunks) { CP_WAIT(1); } else { CP_WAIT(0); }
        __syncthreads();                       // single barrier per chunk
        if (it + 2 < nchunks) {
            int pst = stage + 2; if (pst >= NSTAGE) pst -= NSTAGE;
            load_chunk(sbase + (uint32_t)pst * STAGEB, (it + 2) * GBK);
        }

        const uint32_t st = sbase + (uint32_t)stage * STAGEB;
        const uint32_t aS = st + aLaneOff;
        const uint32_t bS = st + A_MATB + bTransOff;

#pragma unroll
        for (int ks = 0; ks < 4; ks++) {
            uint32_t aa[2][4], bb[16];
#pragma unroll
            for (int mi = 0; mi < 2; mi++)
                ldsm4(aa[mi], aS + mi * 16 * ROWB_A + ks * 32);
#pragma unroll
            for (int p = 0; p < 4; p++)
                ldsm4t(&bb[p * 4], bS + ks * 16 * ROWB_W + p * 32);
#pragma unroll
            for (int mi = 0; mi < 2; mi++)
#pragma unroll
                for (int nj = 0; nj < 8; nj++)
                    mma_f16(acc[mi][nj], aa[mi], &bb[nj * 2]);
        }
        if (++stage >= NSTAGE) stage = 0;
    }

    const int colBase = n0 + warp_n * 64 + (lane & 3) * 2;
    const int rowBase = m0 + warp_m * 32 + (lane >> 2);
    float bias2[8][2];
#pragma unroll
    for (int nj = 0; nj < 8; nj++) {
        const float* bp = bias + (size_t)s * D_H + colBase + nj * 8;
        bias2[nj][0] = bp[0];
        bias2[nj][1] = bp[1];
    }

#pragma unroll
    for (int mi = 0; mi < 2; mi++) {
#pragma unroll
        for (int h = 0; h < 2; h++) {
            const int row = rowBase + mi * 16 + h * 8;
            const size_t rowOff = ((size_t)s * BATCH + row) * D_H;
#pragma unroll
            for (int nj = 0; nj < 8; nj++) {
                float v0 = fmaxf(acc[mi][nj][2 * h]     + bias2[nj][0], 0.0f);
                float v1 = fmaxf(acc[mi][nj][2 * h + 1] + bias2[nj][1], 0.0f);
                __half2 hv = __floats2half2_rn(v0, v1);
                *(__half2*)(Ch + rowOff + colBase + nj * 8) = hv;
            }
        }
    }
}

// ---------------------------------------------------------------------------
// Last layer: out[s,b,o] = act16[s,b,:] . wl[s,:,o] + bl[s,o]
// ---------------------------------------------------------------------------
__global__ void __launch_bounds__(256) layer_out(
    const __half* __restrict__ act, const float* __restrict__ wls,
    const float* __restrict__ bls, float* __restrict__ out)
{
    const int s  = blockIdx.y;
    const int m0 = blockIdx.x * 128;

    __shared__ float As[128][33];
    __shared__ float ws[32 * D_OUT];

    const int tid   = threadIdx.x;
    const int crow  = tid >> 1;
    const int obase = (tid & 1) * 5;

    float acc[5] = {0.f, 0.f, 0.f, 0.f, 0.f};
    const int lr = tid >> 2;
    const int lk = (tid & 3) * 8;

    for (int kt = 0; kt < D_H; kt += 32) {
#pragma unroll
        for (int rr = 0; rr < 2; rr++) {
            int r = lr + rr * 64;
            uint4 v = *(const uint4*)(act + ((size_t)s * BATCH + m0 + r) * D_H + kt + lk);
            const __half2* hp = (const __half2*)&v;
#pragma unroll
            for (int q = 0; q < 4; q++) {
                float2 f = __half22float2(hp[q]);
                As[r][lk + 2 * q]     = f.x;
                As[r][lk + 2 * q + 1] = f.y;
            }
        }
        for (int i = tid; i < 32 * D_OUT; i += 256)
            ws[i] = wls[(size_t)s * D_H * D_OUT + kt * D_OUT + i];
        __syncthreads();
#pragma unroll
        for (int k = 0; k < 32; k++) {
            float a = As[crow][k];
#pragma unroll
            for (int j = 0; j < 5; j++)
                acc[j] = fmaf(a, ws[k * D_OUT + obase + j], acc[j]);
        }
        __syncthreads();
    }
#pragma unroll
    for (int j = 0; j < 5; j++)
        out[((size_t)s * BATCH + m0 + crow) * D_OUT + obase + j] = acc[j] + bls[s * D_OUT + obase + j];
}

// ---------------------------------------------------------------------------
// kernel_launch — R10/R13 structure: plain fork, side stream runs
// layer-1/last-layer preps concurrently with main-stream preps + GEMM0.
// ---------------------------------------------------------------------------
extern "C" void kernel_launch(void* const* d_in, const int* in_sizes, int n_in,
                              void* d_out, int out_size) {
    const float* x   = (const float*)d_in[0];
    const float* wm0 = (const float*)d_in[1];
    const float* wv0 = (const float*)d_in[2];
    const float* bm0 = (const float*)d_in[3];
    const float* bv0 = (const float*)d_in[4];
    const float* wm1 = (const float*)d_in[5];
    const float* wv1 = (const float*)d_in[6];
    const float* bm1 = (const float*)d_in[7];
    const float* bv1 = (const float*)d_in[8];
    const float* wlm = (const float*)d_in[9];
    const float* wlv = (const float*)d_in[10];
    const float* blm = (const float*)d_in[11];
    const float* blv = (const float*)d_in[12];
    const float* we0 = (const float*)d_in[13];
    const float* be0 = (const float*)d_in[14];
    const float* we1 = (const float*)d_in[15];
    const float* be1 = (const float*)d_in[16];
    const float* wel = (const float*)d_in[17];
    const float* bel = (const float*)d_in[18];
    float* out = (float*)d_out;

    __half *x16, *w016, *w116, *a016, *a116, *sig016, *sig116, *wm016, *wm116;
    float *b0, *b1, *wl, *bl;
    cudaGetSymbolAddress((void**)&x16,    g_x16);
    cudaGetSymbolAddress((void**)&w016,   g_w016);
    cudaGetSymbolAddress((void**)&w116,   g_w116);
    cudaGetSymbolAddress((void**)&a016,   g_a016);
    cudaGetSymbolAddress((void**)&a116,   g_a116);
    cudaGetSymbolAddress((void**)&sig016, g_sig016);
    cudaGetSymbolAddress((void**)&sig116, g_sig116);
    cudaGetSymbolAddress((void**)&wm016,  g_wm016);
    cudaGetSymbolAddress((void**)&wm116,  g_wm116);
    cudaGetSymbolAddress((void**)&b0,     g_b0);
    cudaGetSymbolAddress((void**)&b1,     g_b1);
    cudaGetSymbolAddress((void**)&wl,     g_wl);
    cudaGetSymbolAddress((void**)&bl,     g_bl);

    static bool init_done = false;
    static cudaStream_t strm2 = nullptr;
    static cudaEvent_t evFork = nullptr, evJoin = nullptr;
    if (!init_done) {
        cudaFuncSetAttribute(gemm_mma, cudaFuncAttributeMaxDynamicSharedMemorySize, SMEM_TOTAL);
        cudaStreamCreateWithFlags(&strm2, cudaStreamNonBlocking);
        cudaEventCreateWithFlags(&evFork, cudaEventDisableTiming);
        cudaEventCreateWithFlags(&evJoin, cudaEventDisableTiming);
        init_done = true;
    }

    // ---- fork ----
    cudaEventRecord(evFork, 0);
    cudaStreamWaitEvent(strm2, evFork, 0);

    // ---- side stream: everything GEMM0 does NOT need ----
    {
        int n = D_H * D_H;
        prep_sig16<<<(n + 255) / 256, 256, 0, strm2>>>(wv1, sig116, n);
        prep_f2h<<<(n + 255) / 256, 256, 0, strm2>>>(wm1, wm116, n);
        dim3 grid(D_H * D_H / (256 * 8), S_SAMP);
        prep_w<<<grid, 256, 0, strm2>>>(we1, sig116, wm116, w116, D_H, D_H);
        int total = S_SAMP * D_H;
        prep_sample<<<(total + 255) / 256, 256, 0, strm2>>>(be1, bv1, bm1, b1, D_H, total);
        total = S_SAMP * D_H * D_OUT;
        prep_sample<<<(total + 255) / 256, 256, 0, strm2>>>(wel, wlv, wlm, wl, D_H * D_OUT, total);
        total = S_SAMP * D_OUT;
        prep_sample<<<(total + 255) / 256, 256, 0, strm2>>>(bel, blv, blm, bl, D_OUT, total);
        cudaEventRecord(evJoin, strm2);
    }

    // ---- main stream: GEMM0 critical path ----
    {
        int n = D_IN * D_H;
        prep_sig16<<<(n + 255) / 256, 256>>>(wv0, sig016, n);
        prep_f2h<<<(n + 255) / 256, 256>>>(wm0, wm016, n);
        n = BATCH * K0PAD;
        prep_x<<<(n + 255) / 256, 256>>>(x, x16);
        int total = S_SAMP * D_H;
        prep_sample<<<(total + 255) / 256, 256>>>(be0, bv0, bm0, b0, D_H, total);
        dim3 gw(K0PAD * D_H / (256 * 8), S_SAMP);
        prep_w<<<gw, 256>>>(we0, sig016, wm016, w016, D_IN, K0PAD);
        dim3 grid(D_H / GBN, BATCH / GBM, S_SAMP);
        gemm_mma<<<grid, 256, SMEM_TOTAL>>>(x16, 0, K0PAD, w016, b0, a016);
    }

    // ---- join, then layer 1 + output ----
    cudaStreamWaitEvent(0, evJoin, 0);
    {
        dim3 grid(D_H / GBN, BATCH / GBM, S_SAMP);
        gemm_mma<<<grid, 256, SMEM_TOTAL>>>(a016, (size_t)BATCH * D_H, D_H, w116, b1, a116);
    }
    {
        dim3 grid(BATCH / 128, S_SAMP);
        layer_out<<<grid, 256>>>(a116, wl, bl, out);
    }
}

// round 15
// speedup vs baseline: 1.4000x; 1.0065x over previous
#include <cuda_runtime.h>
#include <cuda_fp16.h>
#include <cstdint>
#include <math.h>

#define S_SAMP 32
#define BATCH  1024
#define D_IN   784
#define D_H    1024
#define D_OUT  10
#define K0PAD  832            // 784 padded to multiple of 64

// ---------------------------------------------------------------------------
// Device scratch (static: no cudaMalloc allowed)
// ---------------------------------------------------------------------------
__device__ __half g_x16[(size_t)BATCH * K0PAD];
__device__ __half g_w016[(size_t)S_SAMP * K0PAD * D_H];   // [S][Kpad][N]
__device__ __half g_w116[(size_t)S_SAMP * D_H * D_H];
__device__ __half g_a016[(size_t)S_SAMP * BATCH * D_H];
__device__ __half g_a116[(size_t)S_SAMP * BATCH * D_H];
__device__ __half g_sig016[(size_t)D_IN * D_H];           // fp16 exp(0.5*wv0)
__device__ __half g_sig116[(size_t)D_H * D_H];
__device__ __half g_wm016[(size_t)D_IN * D_H];            // fp16 wm0
__device__ __half g_wm116[(size_t)D_H * D_H];
__device__ float g_b0[S_SAMP * D_H];
__device__ float g_b1[S_SAMP * D_H];
__device__ float g_wl[S_SAMP * D_H * D_OUT];
__device__ float g_bl[S_SAMP * D_OUT];

// ---------------------------------------------------------------------------
// PTX helpers
// ---------------------------------------------------------------------------
__device__ __forceinline__ uint32_t smem_u32(const void* p) {
    uint32_t a;
    asm("{ .reg .u64 t; cvta.to.shared.u64 t, %1; cvt.u32.u64 %0, t; }" : "=r"(a) : "l"(p));
    return a;
}
__device__ __forceinline__ void cp16(uint32_t dst, const void* src) {
    asm volatile("cp.async.cg.shared.global [%0], [%1], 16;" :: "r"(dst), "l"(src) : "memory");
}
#define CP_COMMIT() asm volatile("cp.async.commit_group;" ::: "memory")
#define CP_WAIT(n)  asm volatile("cp.async.wait_group %0;" :: "n"(n) : "memory")

__device__ __forceinline__ void ldsm4(uint32_t* r, uint32_t addr) {
    asm volatile("ldmatrix.sync.aligned.m8n8.x4.shared.b16 {%0,%1,%2,%3}, [%4];"
        : "=r"(r[0]), "=r"(r[1]), "=r"(r[2]), "=r"(r[3]) : "r"(addr));
}
__device__ __forceinline__ void ldsm4t(uint32_t* r, uint32_t addr) {
    asm volatile("ldmatrix.sync.aligned.m8n8.x4.trans.shared.b16 {%0,%1,%2,%3}, [%4];"
        : "=r"(r[0]), "=r"(r[1]), "=r"(r[2]), "=r"(r[3]) : "r"(addr));
}
__device__ __forceinline__ void mma_f16(float* d, const uint32_t* a, const uint32_t* b) {
    asm volatile("mma.sync.aligned.m16n8k16.row.col.f32.f16.f16.f32 "
        "{%0,%1,%2,%3}, {%4,%5,%6,%7}, {%8,%9}, {%0,%1,%2,%3};"
        : "+f"(d[0]), "+f"(d[1]), "+f"(d[2]), "+f"(d[3])
        : "r"(a[0]), "r"(a[1]), "r"(a[2]), "r"(a[3]), "r"(b[0]), "r"(b[1]));
}

// ---------------------------------------------------------------------------
// Prep kernels
// ---------------------------------------------------------------------------
// Fused: sig16 = fp16(exp(0.5*wv)), wm16 = fp16(wm)   (one launch per layer)
__global__ void prep_sw(const float* __restrict__ wv, const float* __restrict__ wm,
                        __half* __restrict__ sig16, __half* __restrict__ wm16, int n) {
    int i = blockIdx.x * blockDim.x + threadIdx.x;
    if (i < n) {
        sig16[i] = __float2half(expf(0.5f * wv[i]));
        wm16[i]  = __float2half(wm[i]);
    }
}

__global__ void prep_x(const float* __restrict__ x, __half* __restrict__ x16) {
    int i = blockIdx.x * blockDim.x + threadIdx.x;
    if (i >= BATCH * K0PAD) return;
    int b = i / K0PAD, k = i - b * K0PAD;
    float v = (k < D_IN) ? x[b * D_IN + k] : 0.0f;
    x16[i] = __float2half(v);
}

// Streaming sampled weights, [S][Kpad][N], 8 elems/thread, fp16 sig/wm planes:
//   w16[s][k][n] = we[s][k][n] * sig16[k][n] + wm16[k][n]   (k >= K -> 0)
__global__ void __launch_bounds__(256) prep_w(
    const float* __restrict__ we, const __half* __restrict__ sig,
    const __half* __restrict__ wm, __half* __restrict__ w16,
    int K, int Kpad)
{
    const int s = blockIdx.y;
    const int i = (blockIdx.x * 256 + threadIdx.x) * 8;
    if (i >= Kpad * D_H) return;
    const int k = i >> 10;
    const int n = i & 1023;

    uint4 outv;
    if (k < K) {
        const float* weP  = we + ((size_t)s * K + k) * D_H + n;
        float4 e0 = *(const float4*)(weP);
        float4 e1 = *(const float4*)(weP + 4);
        uint4 sgv = *(const uint4*)(sig + k * D_H + n);
        uint4 mmv = *(const uint4*)(wm  + k * D_H + n);
        const __half2* sgh = (const __half2*)&sgv;
        const __half2* mmh = (const __half2*)&mmv;
        float2 s0 = __half22float2(sgh[0]), s1 = __half22float2(sgh[1]);
        float2 s2 = __half22float2(sgh[2]), s3 = __half22float2(sgh[3]);
        float2 m0 = __half22float2(mmh[0]), m1 = __half22float2(mmh[1]);
        float2 m2 = __half22float2(mmh[2]), m3 = __half22float2(mmh[3]);
        __half2 h0 = __floats2half2_rn(fmaf(e0.x, s0.x, m0.x), fmaf(e0.y, s0.y, m0.y));
        __half2 h1 = __floats2half2_rn(fmaf(e0.z, s1.x, m1.x), fmaf(e0.w, s1.y, m1.y));
        __half2 h2 = __floats2half2_rn(fmaf(e1.x, s2.x, m2.x), fmaf(e1.y, s2.y, m2.y));
        __half2 h3 = __floats2half2_rn(fmaf(e1.z, s3.x, m3.x), fmaf(e1.w, s3.y, m3.y));
        outv = make_uint4(*(uint32_t*)&h0, *(uint32_t*)&h1, *(uint32_t*)&h2, *(uint32_t*)&h3);
    } else {
        outv = make_uint4(0, 0, 0, 0);
    }
    *(uint4*)(w16 + (size_t)s * Kpad * D_H + i) = outv;
}

__global__ void prep_sample(const float* __restrict__ e, const float* __restrict__ v,
                            const float* __restrict__ m, float* __restrict__ out,
                            int n, int total) {
    int i = blockIdx.x * blockDim.x + threadIdx.x;
    if (i < total) {
        int j = i % n;
        out[i] = fmaf(e[i], expf(0.5f * v[j]), m[j]);
    }
}

// ---------------------------------------------------------------------------
// HMMA GEMM, fp16 single term, 3-stage cp.async pipeline, single barrier/chunk
// ---------------------------------------------------------------------------
#define GBM 128
#define GBN 128
#define GBK 64
#define NSTAGE 3
#define ROWB_A 144
#define A_MATB (128 * ROWB_A)
#define ROWB_W 272
#define W_MATB (64 * ROWB_W)
#define STAGEB (A_MATB + W_MATB)
#define SMEM_TOTAL (NSTAGE * STAGEB)

__global__ void __launch_bounds__(256, 2) gemm_mma(
    const __half* __restrict__ A16, size_t aStrideS, int Kpad,
    const __half* __restrict__ W16,
    const float* __restrict__ bias,
    __half* __restrict__ Ch)
{
    extern __shared__ __align__(16) char dynsmem[];
    const uint32_t sbase = smem_u32(dynsmem);

    const int tid  = threadIdx.x;
    const int wid  = tid >> 5;
    const int lane = tid & 31;
    const int s  = blockIdx.z;
    const int m0 = blockIdx.y * GBM;
    const int n0 = blockIdx.x * GBN;

    const int warp_m = wid >> 1;
    const int warp_n = wid & 1;

    const __half* aG = A16 + (size_t)s * aStrideS + (size_t)m0 * Kpad;
    const __half* wG = W16 + (size_t)s * Kpad * D_H + n0;

    const int firstHalf = (tid < 128);
    const int lrowA = tid & 127;
    const int wj    = tid & 127;
    const int wrow  = wj >> 1;
    const int wgrp  = wj & 1;

    auto load_chunk = [&](uint32_t st, int k0) {
        if (firstHalf) {
#pragma unroll
            for (int c = 0; c < 8; c++)
                cp16(st + (uint32_t)lrowA * ROWB_A + c * 16,
                     aG + (size_t)lrowA * Kpad + k0 + c * 8);
        } else {
#pragma unroll
            for (int c = 0; c < 8; c++)
                cp16(st + A_MATB + (uint32_t)wrow * ROWB_W + wgrp * 128 + c * 16,
                     wG + (size_t)(k0 + wrow) * D_H + wgrp * 64 + c * 8);
        }
        CP_COMMIT();
    };

    const uint32_t aLaneOff = (uint32_t)(lane & 15) * ROWB_A + (uint32_t)(lane >> 4) * 16
                            + (uint32_t)(warp_m * 32) * ROWB_A;
    const int bm = lane >> 3, br = lane & 7;
    const uint32_t bTransOff = (uint32_t)((bm & 1) * 8 + br) * ROWB_W + (uint32_t)(bm >> 1) * 16
                             + (uint32_t)warp_n * 128;

    float acc[2][8][4];
#pragma unroll
    for (int i = 0; i < 2; i++)
#pragma unroll
        for (int j = 0; j < 8; j++)
#pragma unroll
            for (int q = 0; q < 4; q++) acc[i][j][q] = 0.0f;

    const int nchunks = Kpad / GBK;

    // prologue: chunks 0,1 in flight
    load_chunk(sbase, 0);
    if (nchunks > 1) load_chunk(sbase + STAGEB, GBK);

    int stage = 0;
    for (int it = 0; it < nchunks; it++) {
        if (it + 1 < nchunks) { CP_WAIT(1); } else { CP_WAIT(0); }
        __syncthreads();                       // single barrier per chunk
        if (it + 2 < nchunks) {
            int pst = stage + 2; if (pst >= NSTAGE) pst -= NSTAGE;
            load_chunk(sbase + (uint32_t)pst * STAGEB, (it + 2) * GBK);
        }

        const uint32_t st = sbase + (uint32_t)stage * STAGEB;
        const uint32_t aS = st + aLaneOff;
        const uint32_t bS = st + A_MATB + bTransOff;

#pragma unroll
        for (int ks = 0; ks < 4; ks++) {
            uint32_t aa[2][4], bb[16];
#pragma unroll
            for (int mi = 0; mi < 2; mi++)
                ldsm4(aa[mi], aS + mi * 16 * ROWB_A + ks * 32);
#pragma unroll
            for (int p = 0; p < 4; p++)
                ldsm4t(&bb[p * 4], bS + ks * 16 * ROWB_W + p * 32);
#pragma unroll
            for (int mi = 0; mi < 2; mi++)
#pragma unroll
                for (int nj = 0; nj < 8; nj++)
                    mma_f16(acc[mi][nj], aa[mi], &bb[nj * 2]);
        }
        if (++stage >= NSTAGE) stage = 0;
    }

    const int colBase = n0 + warp_n * 64 + (lane & 3) * 2;
    const int rowBase = m0 + warp_m * 32 + (lane >> 2);
    float bias2[8][2];
#pragma unroll
    for (int nj = 0; nj < 8; nj++) {
        const float* bp = bias + (size_t)s * D_H + colBase + nj * 8;
        bias2[nj][0] = bp[0];
        bias2[nj][1] = bp[1];
    }

#pragma unroll
    for (int mi = 0; mi < 2; mi++) {
#pragma unroll
        for (int h = 0; h < 2; h++) {
            const int row = rowBase + mi * 16 + h * 8;
            const size_t rowOff = ((size_t)s * BATCH + row) * D_H;
#pragma unroll
            for (int nj = 0; nj < 8; nj++) {
                float v0 = fmaxf(acc[mi][nj][2 * h]     + bias2[nj][0], 0.0f);
                float v1 = fmaxf(acc[mi][nj][2 * h + 1] + bias2[nj][1], 0.0f);
                __half2 hv = __floats2half2_rn(v0, v1);
                *(__half2*)(Ch + rowOff + colBase + nj * 8) = hv;
            }
        }
    }
}

// ---------------------------------------------------------------------------
// Last layer: out[s,b,o] = act16[s,b,:] . wl[s,:,o] + bl[s,o]
// ---------------------------------------------------------------------------
__global__ void __launch_bounds__(256) layer_out(
    const __half* __restrict__ act, const float* __restrict__ wls,
    const float* __restrict__ bls, float* __restrict__ out)
{
    const int s  = blockIdx.y;
    const int m0 = blockIdx.x * 128;

    __shared__ float As[128][33];
    __shared__ float ws[32 * D_OUT];

    const int tid   = threadIdx.x;
    const int crow  = tid >> 1;
    const int obase = (tid & 1) * 5;

    float acc[5] = {0.f, 0.f, 0.f, 0.f, 0.f};
    const int lr = tid >> 2;
    const int lk = (tid & 3) * 8;

    for (int kt = 0; kt < D_H; kt += 32) {
#pragma unroll
        for (int rr = 0; rr < 2; rr++) {
            int r = lr + rr * 64;
            uint4 v = *(const uint4*)(act + ((size_t)s * BATCH + m0 + r) * D_H + kt + lk);
            const __half2* hp = (const __half2*)&v;
#pragma unroll
            for (int q = 0; q < 4; q++) {
                float2 f = __half22float2(hp[q]);
                As[r][lk + 2 * q]     = f.x;
                As[r][lk + 2 * q + 1] = f.y;
            }
        }
        for (int i = tid; i < 32 * D_OUT; i += 256)
            ws[i] = wls[(size_t)s * D_H * D_OUT + kt * D_OUT + i];
        __syncthreads();
#pragma unroll
        for (int k = 0; k < 32; k++) {
            float a = As[crow][k];
#pragma unroll
            for (int j = 0; j < 5; j++)
                acc[j] = fmaf(a, ws[k * D_OUT + obase + j], acc[j]);
        }
        __syncthreads();
    }
#pragma unroll
    for (int j = 0; j < 5; j++)
        out[((size_t)s * BATCH + m0 + crow) * D_OUT + obase + j] = acc[j] + bls[s * D_OUT + obase + j];
}

// ---------------------------------------------------------------------------
// kernel_launch — fork structure with b0 moved to side-stream head (evB0):
//   stream0: prep_sw0, x, w0, (wait evB0) GEMM0, (wait evJoin) GEMM1, layer_out
//   strm2:   b0 [evB0], prep_sw1, w1, b1, wl, bl [evJoin]
// ---------------------------------------------------------------------------
extern "C" void kernel_launch(void* const* d_in, const int* in_sizes, int n_in,
                              void* d_out, int out_size) {
    const float* x   = (const float*)d_in[0];
    const float* wm0 = (const float*)d_in[1];
    const float* wv0 = (const float*)d_in[2];
    const float* bm0 = (const float*)d_in[3];
    const float* bv0 = (const float*)d_in[4];
    const float* wm1 = (const float*)d_in[5];
    const float* wv1 = (const float*)d_in[6];
    const float* bm1 = (const float*)d_in[7];
    const float* bv1 = (const float*)d_in[8];
    const float* wlm = (const float*)d_in[9];
    const float* wlv = (const float*)d_in[10];
    const float* blm = (const float*)d_in[11];
    const float* blv = (const float*)d_in[12];
    const float* we0 = (const float*)d_in[13];
    const float* be0 = (const float*)d_in[14];
    const float* we1 = (const float*)d_in[15];
    const float* be1 = (const float*)d_in[16];
    const float* wel = (const float*)d_in[17];
    const float* bel = (const float*)d_in[18];
    float* out = (float*)d_out;

    __half *x16, *w016, *w116, *a016, *a116, *sig016, *sig116, *wm016, *wm116;
    float *b0, *b1, *wl, *bl;
    cudaGetSymbolAddress((void**)&x16,    g_x16);
    cudaGetSymbolAddress((void**)&w016,   g_w016);
    cudaGetSymbolAddress((void**)&w116,   g_w116);
    cudaGetSymbolAddress((void**)&a016,   g_a016);
    cudaGetSymbolAddress((void**)&a116,   g_a116);
    cudaGetSymbolAddress((void**)&sig016, g_sig016);
    cudaGetSymbolAddress((void**)&sig116, g_sig116);
    cudaGetSymbolAddress((void**)&wm016,  g_wm016);
    cudaGetSymbolAddress((void**)&wm116,  g_wm116);
    cudaGetSymbolAddress((void**)&b0,     g_b0);
    cudaGetSymbolAddress((void**)&b1,     g_b1);
    cudaGetSymbolAddress((void**)&wl,     g_wl);
    cudaGetSymbolAddress((void**)&bl,     g_bl);

    static bool init_done = false;
    static cudaStream_t strm2 = nullptr;
    static cudaEvent_t evFork = nullptr, evJoin = nullptr, evB0 = nullptr;
    if (!init_done) {
        cudaFuncSetAttribute(gemm_mma, cudaFuncAttributeMaxDynamicSharedMemorySize, SMEM_TOTAL);
        cudaStreamCreateWithFlags(&strm2, cudaStreamNonBlocking);
        cudaEventCreateWithFlags(&evFork, cudaEventDisableTiming);
        cudaEventCreateWithFlags(&evJoin, cudaEventDisableTiming);
        cudaEventCreateWithFlags(&evB0,   cudaEventDisableTiming);
        init_done = true;
    }

    // ---- fork ----
    cudaEventRecord(evFork, 0);
    cudaStreamWaitEvent(strm2, evFork, 0);

    // ---- side stream: b0 first (GEMM0 waits on evB0), then layer-1/last prep ----
    {
        int total = S_SAMP * D_H;
        prep_sample<<<(total + 255) / 256, 256, 0, strm2>>>(be0, bv0, bm0, b0, D_H, total);
        cudaEventRecord(evB0, strm2);

        int n = D_H * D_H;
        prep_sw<<<(n + 255) / 256, 256, 0, strm2>>>(wv1, wm1, sig116, wm116, n);
        dim3 grid(D_H * D_H / (256 * 8), S_SAMP);
        prep_w<<<grid, 256, 0, strm2>>>(we1, sig116, wm116, w116, D_H, D_H);
        prep_sample<<<(total + 255) / 256, 256, 0, strm2>>>(be1, bv1, bm1, b1, D_H, total);
        total = S_SAMP * D_H * D_OUT;
        prep_sample<<<(total + 255) / 256, 256, 0, strm2>>>(wel, wlv, wlm, wl, D_H * D_OUT, total);
        total = S_SAMP * D_OUT;
        prep_sample<<<(total + 255) / 256, 256, 0, strm2>>>(bel, blv, blm, bl, D_OUT, total);
        cudaEventRecord(evJoin, strm2);
    }

    // ---- main stream: GEMM0 critical path ----
    {
        int n = D_IN * D_H;
        prep_sw<<<(n + 255) / 256, 256>>>(wv0, wm0, sig016, wm016, n);
        n = BATCH * K0PAD;
        prep_x<<<(n + 255) / 256, 256>>>(x, x16);
        dim3 gw(K0PAD * D_H / (256 * 8), S_SAMP);
        prep_w<<<gw, 256>>>(we0, sig016, wm016, w016, D_IN, K0PAD);
        cudaStreamWaitEvent(0, evB0, 0);
        dim3 grid(D_H / GBN, BATCH / GBM, S_SAMP);
        gemm_mma<<<grid, 256, SMEM_TOTAL>>>(x16, 0, K0PAD, w016, b0, a016);
    }

    // ---- join, then layer 1 + output ----
    cudaStreamWaitEvent(0, evJoin, 0);
    {
        dim3 grid(D_H / GBN, BATCH / GBM, S_SAMP);
        gemm_mma<<<grid, 256, SMEM_TOTAL>>>(a016, (size_t)BATCH * D_H, D_H, w116, b1, a116);
    }
    {
        dim3 grid(BATCH / 128, S_SAMP);
        layer_out<<<grid, 256>>>(a116, wl, bl, out);
    }
}

// round 16
// speedup vs baseline: 1.4269x; 1.0192x over previous
#include <cuda_runtime.h>
#include <cuda_fp16.h>
#include <cstdint>
#include <math.h>

#define S_SAMP 32
#define BATCH  1024
#define D_IN   784
#define D_H    1024
#define D_OUT  10
#define K0PAD  832            // 784 padded to multiple of 64

// ---------------------------------------------------------------------------
// Device scratch (static: no cudaMalloc allowed)
// ---------------------------------------------------------------------------
__device__ __half g_x16[(size_t)BATCH * K0PAD];
__device__ __half g_w016[(size_t)S_SAMP * K0PAD * D_H];   // [S][Kpad][N]
__device__ __half g_w116[(size_t)S_SAMP * D_H * D_H];
__device__ __half g_a016[(size_t)S_SAMP * BATCH * D_H];
__device__ __half g_a116[(size_t)S_SAMP * BATCH * D_H];
__device__ __half g_sig016[(size_t)D_IN * D_H];           // fp16 exp(0.5*wv0)
__device__ __half g_sig116[(size_t)D_H * D_H];
__device__ __half g_wm016[(size_t)D_IN * D_H];            // fp16 wm0
__device__ __half g_wm116[(size_t)D_H * D_H];
__device__ float g_b0[S_SAMP * D_H];
__device__ float g_b1[S_SAMP * D_H];
__device__ float g_wl[S_SAMP * D_H * D_OUT];
__device__ float g_bl[S_SAMP * D_OUT];

// ---------------------------------------------------------------------------
// PTX helpers
// ---------------------------------------------------------------------------
__device__ __forceinline__ uint32_t smem_u32(const void* p) {
    uint32_t a;
    asm("{ .reg .u64 t; cvta.to.shared.u64 t, %1; cvt.u32.u64 %0, t; }" : "=r"(a) : "l"(p));
    return a;
}
__device__ __forceinline__ void cp16(uint32_t dst, const void* src) {
    asm volatile("cp.async.cg.shared.global [%0], [%1], 16;" :: "r"(dst), "l"(src) : "memory");
}
#define CP_COMMIT() asm volatile("cp.async.commit_group;" ::: "memory")
#define CP_WAIT(n)  asm volatile("cp.async.wait_group %0;" :: "n"(n) : "memory")

__device__ __forceinline__ void ldsm4(uint32_t* r, uint32_t addr) {
    asm volatile("ldmatrix.sync.aligned.m8n8.x4.shared.b16 {%0,%1,%2,%3}, [%4];"
        : "=r"(r[0]), "=r"(r[1]), "=r"(r[2]), "=r"(r[3]) : "r"(addr));
}
__device__ __forceinline__ void ldsm4t(uint32_t* r, uint32_t addr) {
    asm volatile("ldmatrix.sync.aligned.m8n8.x4.trans.shared.b16 {%0,%1,%2,%3}, [%4];"
        : "=r"(r[0]), "=r"(r[1]), "=r"(r[2]), "=r"(r[3]) : "r"(addr));
}
__device__ __forceinline__ void mma_f16(float* d, const uint32_t* a, const uint32_t* b) {
    asm volatile("mma.sync.aligned.m16n8k16.row.col.f32.f16.f16.f32 "
        "{%0,%1,%2,%3}, {%4,%5,%6,%7}, {%8,%9}, {%0,%1,%2,%3};"
        : "+f"(d[0]), "+f"(d[1]), "+f"(d[2]), "+f"(d[3])
        : "r"(a[0]), "r"(a[1]), "r"(a[2]), "r"(a[3]), "r"(b[0]), "r"(b[1]));
}

// ---------------------------------------------------------------------------
// Prep kernels
// ---------------------------------------------------------------------------
__global__ void prep_sw(const float* __restrict__ wv, const float* __restrict__ wm,
                        __half* __restrict__ sig16, __half* __restrict__ wm16, int n) {
    int i = blockIdx.x * blockDim.x + threadIdx.x;
    if (i < n) {
        sig16[i] = __float2half(expf(0.5f * wv[i]));
        wm16[i]  = __float2half(wm[i]);
    }
}

__global__ void prep_x(const float* __restrict__ x, __half* __restrict__ x16) {
    int i = blockIdx.x * blockDim.x + threadIdx.x;
    if (i >= BATCH * K0PAD) return;
    int b = i / K0PAD, k = i - b * K0PAD;
    float v = (k < D_IN) ? x[b * D_IN + k] : 0.0f;
    x16[i] = __float2half(v);
}

__global__ void __launch_bounds__(256) prep_w(
    const float* __restrict__ we, const __half* __restrict__ sig,
    const __half* __restrict__ wm, __half* __restrict__ w16,
    int K, int Kpad)
{
    const int s = blockIdx.y;
    const int i = (blockIdx.x * 256 + threadIdx.x) * 8;
    if (i >= Kpad * D_H) return;
    const int k = i >> 10;
    const int n = i & 1023;

    uint4 outv;
    if (k < K) {
        const float* weP  = we + ((size_t)s * K + k) * D_H + n;
        float4 e0 = *(const float4*)(weP);
        float4 e1 = *(const float4*)(weP + 4);
        uint4 sgv = *(const uint4*)(sig + k * D_H + n);
        uint4 mmv = *(const uint4*)(wm  + k * D_H + n);
        const __half2* sgh = (const __half2*)&sgv;
        const __half2* mmh = (const __half2*)&mmv;
        float2 s0 = __half22float2(sgh[0]), s1 = __half22float2(sgh[1]);
        float2 s2 = __half22float2(sgh[2]), s3 = __half22float2(sgh[3]);
        float2 m0 = __half22float2(mmh[0]), m1 = __half22float2(mmh[1]);
        float2 m2 = __half22float2(mmh[2]), m3 = __half22float2(mmh[3]);
        __half2 h0 = __floats2half2_rn(fmaf(e0.x, s0.x, m0.x), fmaf(e0.y, s0.y, m0.y));
        __half2 h1 = __floats2half2_rn(fmaf(e0.z, s1.x, m1.x), fmaf(e0.w, s1.y, m1.y));
        __half2 h2 = __floats2half2_rn(fmaf(e1.x, s2.x, m2.x), fmaf(e1.y, s2.y, m2.y));
        __half2 h3 = __floats2half2_rn(fmaf(e1.z, s3.x, m3.x), fmaf(e1.w, s3.y, m3.y));
        outv = make_uint4(*(uint32_t*)&h0, *(uint32_t*)&h1, *(uint32_t*)&h2, *(uint32_t*)&h3);
    } else {
        outv = make_uint4(0, 0, 0, 0);
    }
    *(uint4*)(w16 + (size_t)s * Kpad * D_H + i) = outv;
}

__global__ void prep_sample(const float* __restrict__ e, const float* __restrict__ v,
                            const float* __restrict__ m, float* __restrict__ out,
                            int n, int total) {
    int i = blockIdx.x * blockDim.x + threadIdx.x;
    if (i < total) {
        int j = i % n;
        out[i] = fmaf(e[i], expf(0.5f * v[j]), m[j]);
    }
}

// ---------------------------------------------------------------------------
// HMMA GEMM, fp16 single term, 3-stage pipeline, single barrier/chunk.
// CTA tile 256x128x64, 512 threads (16 warps, warp tile 64x32).
// ---------------------------------------------------------------------------
#define GBM 256
#define GBN 128
#define GBK 64
#define NSTAGE 3
#define ROWB_A 144                   // A row: 128B data + 16 pad
#define A_MATB (256 * ROWB_A)        // 36864 B
#define ROWB_W 272                   // W k-row: 256B data + 16 pad
#define W_MATB (64 * ROWB_W)         // 17408 B
#define STAGEB (A_MATB + W_MATB)     // 54272 B
#define SMEM_TOTAL (NSTAGE * STAGEB) // 162816 B

__global__ void __launch_bounds__(512, 1) gemm_mma(
    const __half* __restrict__ A16, size_t aStrideS, int Kpad,
    const __half* __restrict__ W16,
    const float* __restrict__ bias,
    __half* __restrict__ Ch)
{
    extern __shared__ __align__(16) char dynsmem[];
    const uint32_t sbase = smem_u32(dynsmem);

    const int tid  = threadIdx.x;
    const int wid  = tid >> 5;         // 0..15
    const int lane = tid & 31;
    const int s  = blockIdx.z;
    const int m0 = blockIdx.y * GBM;
    const int n0 = blockIdx.x * GBN;

    const int warp_m = wid >> 2;       // 0..3 -> 64-row strip
    const int warp_n = wid & 3;        // 0..3 -> 32-col strip

    const __half* aG = A16 + (size_t)s * aStrideS + (size_t)m0 * Kpad;
    const __half* wG = W16 + (size_t)s * Kpad * D_H + n0;

    // Loaders: tid<256 -> A row tid, 8 cp16; tid>=256 -> W row (wj>>2), quarter (wj&3), 4 cp16
    const int firstHalf = (tid < 256);
    const int lrowA = tid & 255;
    const int wj    = tid & 255;
    const int wrow  = wj >> 2;         // 0..63
    const int wgrp  = wj & 3;          // 4 x 64B quarters of the 256B row

    auto load_chunk = [&](uint32_t st, int k0) {
        if (firstHalf) {
#pragma unroll
            for (int c = 0; c < 8; c++)
                cp16(st + (uint32_t)lrowA * ROWB_A + c * 16,
                     aG + (size_t)lrowA * Kpad + k0 + c * 8);
        } else {
#pragma unroll
            for (int c = 0; c < 4; c++)
                cp16(st + A_MATB + (uint32_t)wrow * ROWB_W + wgrp * 64 + c * 16,
                     wG + (size_t)(k0 + wrow) * D_H + wgrp * 32 + c * 8);
        }
        CP_COMMIT();
    };

    const uint32_t aLaneOff = (uint32_t)(lane & 15) * ROWB_A + (uint32_t)(lane >> 4) * 16
                            + (uint32_t)(warp_m * 64) * ROWB_A;
    const int bm = lane >> 3, br = lane & 7;
    const uint32_t bTransOff = (uint32_t)((bm & 1) * 8 + br) * ROWB_W + (uint32_t)(bm >> 1) * 16
                             + (uint32_t)warp_n * 64;   // 32 cols * 2B

    float acc[4][4][4];
#pragma unroll
    for (int i = 0; i < 4; i++)
#pragma unroll
        for (int j = 0; j < 4; j++)
#pragma unroll
            for (int q = 0; q < 4; q++) acc[i][j][q] = 0.0f;

    const int nchunks = Kpad / GBK;

    // prologue: chunks 0,1 in flight
    load_chunk(sbase, 0);
    if (nchunks > 1) load_chunk(sbase + STAGEB, GBK);

    int stage = 0;
    for (int it = 0; it < nchunks; it++) {
        if (it + 1 < nchunks) { CP_WAIT(1); } else { CP_WAIT(0); }
        __syncthreads();                       // single barrier per chunk
        if (it + 2 < nchunks) {
            int pst = stage + 2; if (pst >= NSTAGE) pst -= NSTAGE;
            load_chunk(sbase + (uint32_t)pst * STAGEB, (it + 2) * GBK);
        }

        const uint32_t st = sbase + (uint32_t)stage * STAGEB;
        const uint32_t aS = st + aLaneOff;
        const uint32_t bS = st + A_MATB + bTransOff;

#pragma unroll
        for (int ks = 0; ks < 4; ks++) {
            uint32_t aa[4][4], bb[8];
#pragma unroll
            for (int mi = 0; mi < 4; mi++)
                ldsm4(aa[mi], aS + mi * 16 * ROWB_A + ks * 32);
#pragma unroll
            for (int p = 0; p < 2; p++)
                ldsm4t(&bb[p * 4], bS + ks * 16 * ROWB_W + p * 32);
#pragma unroll
            for (int mi = 0; mi < 4; mi++)
#pragma unroll
                for (int nj = 0; nj < 4; nj++)
                    mma_f16(acc[mi][nj], aa[mi], &bb[nj * 2]);
        }
        if (++stage >= NSTAGE) stage = 0;
    }

    // ---- epilogue: bias + relu -> fp16 ----
    const int colBase = n0 + warp_n * 32 + (lane & 3) * 2;
    const int rowBase = m0 + warp_m * 64 + (lane >> 2);
    float bias2[4][2];
#pragma unroll
    for (int nj = 0; nj < 4; nj++) {
        const float* bp = bias + (size_t)s * D_H + colBase + nj * 8;
        bias2[nj][0] = bp[0];
        bias2[nj][1] = bp[1];
    }

#pragma unroll
    for (int mi = 0; mi < 4; mi++) {
#pragma unroll
        for (int h = 0; h < 2; h++) {
            const int row = rowBase + mi * 16 + h * 8;
            const size_t rowOff = ((size_t)s * BATCH + row) * D_H;
#pragma unroll
            for (int nj = 0; nj < 4; nj++) {
                float v0 = fmaxf(acc[mi][nj][2 * h]     + bias2[nj][0], 0.0f);
                float v1 = fmaxf(acc[mi][nj][2 * h + 1] + bias2[nj][1], 0.0f);
                __half2 hv = __floats2half2_rn(v0, v1);
                *(__half2*)(Ch + rowOff + colBase + nj * 8) = hv;
            }
        }
    }
}

// ---------------------------------------------------------------------------
// Last layer: out[s,b,o] = act16[s,b,:] . wl[s,:,o] + bl[s,o]
// ---------------------------------------------------------------------------
__global__ void __launch_bounds__(256) layer_out(
    const __half* __restrict__ act, const float* __restrict__ wls,
    const float* __restrict__ bls, float* __restrict__ out)
{
    const int s  = blockIdx.y;
    const int m0 = blockIdx.x * 128;

    __shared__ float As[128][33];
    __shared__ float ws[32 * D_OUT];

    const int tid   = threadIdx.x;
    const int crow  = tid >> 1;
    const int obase = (tid & 1) * 5;

    float acc[5] = {0.f, 0.f, 0.f, 0.f, 0.f};
    const int lr = tid >> 2;
    const int lk = (tid & 3) * 8;

    for (int kt = 0; kt < D_H; kt += 32) {
#pragma unroll
        for (int rr = 0; rr < 2; rr++) {
            int r = lr + rr * 64;
            uint4 v = *(const uint4*)(act + ((size_t)s * BATCH + m0 + r) * D_H + kt + lk);
            const __half2* hp = (const __half2*)&v;
#pragma unroll
            for (int q = 0; q < 4; q++) {
                float2 f = __half22float2(hp[q]);
                As[r][lk + 2 * q]     = f.x;
                As[r][lk + 2 * q + 1] = f.y;
            }
        }
        for (int i = tid; i < 32 * D_OUT; i += 256)
            ws[i] = wls[(size_t)s * D_H * D_OUT + kt * D_OUT + i];
        __syncthreads();
#pragma unroll
        for (int k = 0; k < 32; k++) {
            float a = As[crow][k];
#pragma unroll
            for (int j = 0; j < 5; j++)
                acc[j] = fmaf(a, ws[k * D_OUT + obase + j], acc[j]);
        }
        __syncthreads();
    }
#pragma unroll
    for (int j = 0; j < 5; j++)
        out[((size_t)s * BATCH + m0 + crow) * D_OUT + obase + j] = acc[j] + bls[s * D_OUT + obase + j];
}

// ---------------------------------------------------------------------------
// kernel_launch — fork structure with b0 on side-stream head (evB0)
// ---------------------------------------------------------------------------
extern "C" void kernel_launch(void* const* d_in, const int* in_sizes, int n_in,
                              void* d_out, int out_size) {
    const float* x   = (const float*)d_in[0];
    const float* wm0 = (const float*)d_in[1];
    const float* wv0 = (const float*)d_in[2];
    const float* bm0 = (const float*)d_in[3];
    const float* bv0 = (const float*)d_in[4];
    const float* wm1 = (const float*)d_in[5];
    const float* wv1 = (const float*)d_in[6];
    const float* bm1 = (const float*)d_in[7];
    const float* bv1 = (const float*)d_in[8];
    const float* wlm = (const float*)d_in[9];
    const float* wlv = (const float*)d_in[10];
    const float* blm = (const float*)d_in[11];
    const float* blv = (const float*)d_in[12];
    const float* we0 = (const float*)d_in[13];
    const float* be0 = (const float*)d_in[14];
    const float* we1 = (const float*)d_in[15];
    const float* be1 = (const float*)d_in[16];
    const float* wel = (const float*)d_in[17];
    const float* bel = (const float*)d_in[18];
    float* out = (float*)d_out;

    __half *x16, *w016, *w116, *a016, *a116, *sig016, *sig116, *wm016, *wm116;
    float *b0, *b1, *wl, *bl;
    cudaGetSymbolAddress((void**)&x16,    g_x16);
    cudaGetSymbolAddress((void**)&w016,   g_w016);
    cudaGetSymbolAddress((void**)&w116,   g_w116);
    cudaGetSymbolAddress((void**)&a016,   g_a016);
    cudaGetSymbolAddress((void**)&a116,   g_a116);
    cudaGetSymbolAddress((void**)&sig016, g_sig016);
    cudaGetSymbolAddress((void**)&sig116, g_sig116);
    cudaGetSymbolAddress((void**)&wm016,  g_wm016);
    cudaGetSymbolAddress((void**)&wm116,  g_wm116);
    cudaGetSymbolAddress((void**)&b0,     g_b0);
    cudaGetSymbolAddress((void**)&b1,     g_b1);
    cudaGetSymbolAddress((void**)&wl,     g_wl);
    cudaGetSymbolAddress((void**)&bl,     g_bl);

    static bool init_done = false;
    static cudaStream_t strm2 = nullptr;
    static cudaEvent_t evFork = nullptr, evJoin = nullptr, evB0 = nullptr;
    if (!init_done) {
        cudaFuncSetAttribute(gemm_mma, cudaFuncAttributeMaxDynamicSharedMemorySize, SMEM_TOTAL);
        cudaStreamCreateWithFlags(&strm2, cudaStreamNonBlocking);
        cudaEventCreateWithFlags(&evFork, cudaEventDisableTiming);
        cudaEventCreateWithFlags(&evJoin, cudaEventDisableTiming);
        cudaEventCreateWithFlags(&evB0,   cudaEventDisableTiming);
        init_done = true;
    }

    // ---- fork ----
    cudaEventRecord(evFork, 0);
    cudaStreamWaitEvent(strm2, evFork, 0);

    // ---- side stream: b0 first, then layer-1/last-layer preps ----
    {
        int total = S_SAMP * D_H;
        prep_sample<<<(total + 255) / 256, 256, 0, strm2>>>(be0, bv0, bm0, b0, D_H, total);
        cudaEventRecord(evB0, strm2);

        int n = D_H * D_H;
        prep_sw<<<(n + 255) / 256, 256, 0, strm2>>>(wv1, wm1, sig116, wm116, n);
        dim3 grid(D_H * D_H / (256 * 8), S_SAMP);
        prep_w<<<grid, 256, 0, strm2>>>(we1, sig116, wm116, w116, D_H, D_H);
        prep_sample<<<(total + 255) / 256, 256, 0, strm2>>>(be1, bv1, bm1, b1, D_H, total);
        total = S_SAMP * D_H * D_OUT;
        prep_sample<<<(total + 255) / 256, 256, 0, strm2>>>(wel, wlv, wlm, wl, D_H * D_OUT, total);
        total = S_SAMP * D_OUT;
        prep_sample<<<(total + 255) / 256, 256, 0, strm2>>>(bel, blv, blm, bl, D_OUT, total);
        cudaEventRecord(evJoin, strm2);
    }

    // ---- main stream: GEMM0 critical path ----
    {
        int n = D_IN * D_H;
        prep_sw<<<(n + 255) / 256, 256>>>(wv0, wm0, sig016, wm016, n);
        n = BATCH * K0PAD;
        prep_x<<<(n + 255) / 256, 256>>>(x, x16);
        dim3 gw(K0PAD * D_H / (256 * 8), S_SAMP);
        prep_w<<<gw, 256>>>(we0, sig016, wm016, w016, D_IN, K0PAD);
        cudaStreamWaitEvent(0, evB0, 0);
        dim3 grid(D_H / GBN, BATCH / GBM, S_SAMP);
        gemm_mma<<<grid, 512, SMEM_TOTAL>>>(x16, 0, K0PAD, w016, b0, a016);
    }

    // ---- join, then layer 1 + output ----
    cudaStreamWaitEvent(0, evJoin, 0);
    {
        dim3 grid(D_H / GBN, BATCH / GBM, S_SAMP);
        gemm_mma<<<grid, 512, SMEM_TOTAL>>>(a016, (size_t)BATCH * D_H, D_H, w116, b1, a116);
    }
    {
        dim3 grid(BATCH / 128, S_SAMP);
        layer_out<<<grid, 256>>>(a116, wl, bl, out);
    }
}

// round 17
// speedup vs baseline: 1.5670x; 1.0982x over previous
#include <cuda_runtime.h>
#include <cuda_fp16.h>
#include <cstdint>
#include <math.h>

#define S_SAMP 32
#define BATCH  1024
#define D_IN   784
#define D_H    1024
#define D_OUT  10
#define K0PAD  832            // 784 padded to multiple of 64
#define NSLICE 8              // D_H / GBN

// ---------------------------------------------------------------------------
// Device scratch (static: no cudaMalloc allowed)
// ---------------------------------------------------------------------------
__device__ __half g_x16[(size_t)BATCH * K0PAD];
__device__ __half g_w016[(size_t)S_SAMP * K0PAD * D_H];   // [S][Kpad][N]
__device__ __half g_w116[(size_t)S_SAMP * D_H * D_H];
__device__ __half g_a016[(size_t)S_SAMP * BATCH * D_H];
__device__ __half g_sig016[(size_t)D_IN * D_H];
__device__ __half g_sig116[(size_t)D_H * D_H];
__device__ __half g_wm016[(size_t)D_IN * D_H];
__device__ __half g_wm116[(size_t)D_H * D_H];
__device__ float g_b0[S_SAMP * D_H];
__device__ float g_b1[S_SAMP * D_H];
__device__ float g_wl[S_SAMP * D_H * D_OUT];
__device__ float g_bl[S_SAMP * D_OUT];
__device__ float g_part[(size_t)NSLICE * S_SAMP * BATCH * D_OUT];  // 10.5 MB

// ---------------------------------------------------------------------------
// PTX helpers
// ---------------------------------------------------------------------------
__device__ __forceinline__ uint32_t smem_u32(const void* p) {
    uint32_t a;
    asm("{ .reg .u64 t; cvta.to.shared.u64 t, %1; cvt.u32.u64 %0, t; }" : "=r"(a) : "l"(p));
    return a;
}
__device__ __forceinline__ void cp16(uint32_t dst, const void* src) {
    asm volatile("cp.async.cg.shared.global [%0], [%1], 16;" :: "r"(dst), "l"(src) : "memory");
}
#define CP_COMMIT() asm volatile("cp.async.commit_group;" ::: "memory")
#define CP_WAIT(n)  asm volatile("cp.async.wait_group %0;" :: "n"(n) : "memory")

__device__ __forceinline__ void ldsm4(uint32_t* r, uint32_t addr) {
    asm volatile("ldmatrix.sync.aligned.m8n8.x4.shared.b16 {%0,%1,%2,%3}, [%4];"
        : "=r"(r[0]), "=r"(r[1]), "=r"(r[2]), "=r"(r[3]) : "r"(addr));
}
__device__ __forceinline__ void ldsm4t(uint32_t* r, uint32_t addr) {
    asm volatile("ldmatrix.sync.aligned.m8n8.x4.trans.shared.b16 {%0,%1,%2,%3}, [%4];"
        : "=r"(r[0]), "=r"(r[1]), "=r"(r[2]), "=r"(r[3]) : "r"(addr));
}
__device__ __forceinline__ void mma_f16(float* d, const uint32_t* a, const uint32_t* b) {
    asm volatile("mma.sync.aligned.m16n8k16.row.col.f32.f16.f16.f32 "
        "{%0,%1,%2,%3}, {%4,%5,%6,%7}, {%8,%9}, {%0,%1,%2,%3};"
        : "+f"(d[0]), "+f"(d[1]), "+f"(d[2]), "+f"(d[3])
        : "r"(a[0]), "r"(a[1]), "r"(a[2]), "r"(a[3]), "r"(b[0]), "r"(b[1]));
}
__device__ __forceinline__ uint32_t pack_h2(float a, float b) {
    __half2 h = __floats2half2_rn(a, b);
    return *(uint32_t*)&h;
}

// ---------------------------------------------------------------------------
// Prep kernels
// ---------------------------------------------------------------------------
__global__ void prep_sw(const float* __restrict__ wv, const float* __restrict__ wm,
                        __half* __restrict__ sig16, __half* __restrict__ wm16, int n) {
    int i = blockIdx.x * blockDim.x + threadIdx.x;
    if (i < n) {
        sig16[i] = __float2half(expf(0.5f * wv[i]));
        wm16[i]  = __float2half(wm[i]);
    }
}

__global__ void prep_x(const float* __restrict__ x, __half* __restrict__ x16) {
    int i = blockIdx.x * blockDim.x + threadIdx.x;
    if (i >= BATCH * K0PAD) return;
    int b = i / K0PAD, k = i - b * K0PAD;
    float v = (k < D_IN) ? x[b * D_IN + k] : 0.0f;
    x16[i] = __float2half(v);
}

__global__ void __launch_bounds__(256) prep_w(
    const float* __restrict__ we, const __half* __restrict__ sig,
    const __half* __restrict__ wm, __half* __restrict__ w16,
    int K, int Kpad)
{
    const int s = blockIdx.y;
    const int i = (blockIdx.x * 256 + threadIdx.x) * 8;
    if (i >= Kpad * D_H) return;
    const int k = i >> 10;
    const int n = i & 1023;

    uint4 outv;
    if (k < K) {
        const float* weP  = we + ((size_t)s * K + k) * D_H + n;
        float4 e0 = *(const float4*)(weP);
        float4 e1 = *(const float4*)(weP + 4);
        uint4 sgv = *(const uint4*)(sig + k * D_H + n);
        uint4 mmv = *(const uint4*)(wm  + k * D_H + n);
        const __half2* sgh = (const __half2*)&sgv;
        const __half2* mmh = (const __half2*)&mmv;
        float2 s0 = __half22float2(sgh[0]), s1 = __half22float2(sgh[1]);
        float2 s2 = __half22float2(sgh[2]), s3 = __half22float2(sgh[3]);
        float2 m0 = __half22float2(mmh[0]), m1 = __half22float2(mmh[1]);
        float2 m2 = __half22float2(mmh[2]), m3 = __half22float2(mmh[3]);
        __half2 h0 = __floats2half2_rn(fmaf(e0.x, s0.x, m0.x), fmaf(e0.y, s0.y, m0.y));
        __half2 h1 = __floats2half2_rn(fmaf(e0.z, s1.x, m1.x), fmaf(e0.w, s1.y, m1.y));
        __half2 h2 = __floats2half2_rn(fmaf(e1.x, s2.x, m2.x), fmaf(e1.y, s2.y, m2.y));
        __half2 h3 = __floats2half2_rn(fmaf(e1.z, s3.x, m3.x), fmaf(e1.w, s3.y, m3.y));
        outv = make_uint4(*(uint32_t*)&h0, *(uint32_t*)&h1, *(uint32_t*)&h2, *(uint32_t*)&h3);
    } else {
        outv = make_uint4(0, 0, 0, 0);
    }
    *(uint4*)(w16 + (size_t)s * Kpad * D_H + i) = outv;
}

__global__ void prep_sample(const float* __restrict__ e, const float* __restrict__ v,
                            const float* __restrict__ m, float* __restrict__ out,
                            int n, int total) {
    int i = blockIdx.x * blockDim.x + threadIdx.x;
    if (i < total) {
        int j = i % n;
        out[i] = fmaf(e[i], expf(0.5f * v[j]), m[j]);
    }
}

// Final reduce: out[s,b,o] = bl[s,o] + sum_j part[j][s,b,o]
__global__ void reduce_out(const float* __restrict__ part, const float* __restrict__ bl,
                           float* __restrict__ out) {
    int i = blockIdx.x * blockDim.x + threadIdx.x;
    const int total = S_SAMP * BATCH * D_OUT;
    if (i >= total) return;
    int s = i / (BATCH * D_OUT);
    int o = i % D_OUT;
    float sum = bl[s * D_OUT + o];
#pragma unroll
    for (int j = 0; j < NSLICE; j++)
        sum += part[(size_t)j * total + i];
    out[i] = sum;
}

// ---------------------------------------------------------------------------
// HMMA GEMM, fp16 single term, 3-stage pipeline, single barrier/chunk.
// CTA tile 256x128x64, 512 threads (16 warps, warp tile 64x32).
// mode 0: epilogue writes relu(acc+bias) as fp16 to Ch (feeds GEMM1).
// mode 1: fused final layer — relu(acc+bias) -> A-frags, x wl (B in smem),
//         deterministic cross-warp reduce, write per-slice partials.
// ---------------------------------------------------------------------------
#define GBM 256
#define GBN 128
#define GBK 64
#define NSTAGE 3
#define ROWB_A 144
#define A_MATB (256 * ROWB_A)
#define ROWB_W 272
#define W_MATB (64 * ROWB_W)
#define STAGEB (A_MATB + W_MATB)
#define SMEM_TOTAL (NSTAGE * STAGEB) // 162816 B

__global__ void __launch_bounds__(512, 1) gemm_mma(
    const __half* __restrict__ A16, size_t aStrideS, int Kpad,
    const __half* __restrict__ W16,
    const float* __restrict__ bias,
    __half* __restrict__ Ch,
    const float* __restrict__ wls,   // mode 1: sampled last-layer W [S][D_H][10]
    float* __restrict__ Pout,        // mode 1: partials [NSLICE][S][B][10]
    int mode)
{
    extern __shared__ __align__(16) char dynsmem[];
    const uint32_t sbase = smem_u32(dynsmem);

    const int tid  = threadIdx.x;
    const int wid  = tid >> 5;
    const int lane = tid & 31;
    const int s  = blockIdx.z;
    const int m0 = blockIdx.y * GBM;
    const int n0 = blockIdx.x * GBN;

    const int warp_m = wid >> 2;       // 0..3 -> 64-row strip
    const int warp_n = wid & 3;        // 0..3 -> 32-col strip

    const __half* aG = A16 + (size_t)s * aStrideS + (size_t)m0 * Kpad;
    const __half* wG = W16 + (size_t)s * Kpad * D_H + n0;

    const int firstHalf = (tid < 256);
    const int lrowA = tid & 255;
    const int wj    = tid & 255;
    const int wrow  = wj >> 2;
    const int wgrp  = wj & 3;

    auto load_chunk = [&](uint32_t st, int k0) {
        if (firstHalf) {
#pragma unroll
            for (int c = 0; c < 8; c++)
                cp16(st + (uint32_t)lrowA * ROWB_A + c * 16,
                     aG + (size_t)lrowA * Kpad + k0 + c * 8);
        } else {
#pragma unroll
            for (int c = 0; c < 4; c++)
                cp16(st + A_MATB + (uint32_t)wrow * ROWB_W + wgrp * 64 + c * 16,
                     wG + (size_t)(k0 + wrow) * D_H + wgrp * 32 + c * 8);
        }
        CP_COMMIT();
    };

    const uint32_t aLaneOff = (uint32_t)(lane & 15) * ROWB_A + (uint32_t)(lane >> 4) * 16
                            + (uint32_t)(warp_m * 64) * ROWB_A;
    const int bm = lane >> 3, br = lane & 7;
    const uint32_t bTransOff = (uint32_t)((bm & 1) * 8 + br) * ROWB_W + (uint32_t)(bm >> 1) * 16
                             + (uint32_t)warp_n * 64;

    float acc[4][4][4];
#pragma unroll
    for (int i = 0; i < 4; i++)
#pragma unroll
        for (int j = 0; j < 4; j++)
#pragma unroll
            for (int q = 0; q < 4; q++) acc[i][j][q] = 0.0f;

    const int nchunks = Kpad / GBK;
    load_chunk(sbase, 0);
    if (nchunks > 1) load_chunk(sbase + STAGEB, GBK);

    int stage = 0;
    for (int it = 0; it < nchunks; it++) {
        if (it + 1 < nchunks) { CP_WAIT(1); } else { CP_WAIT(0); }
        __syncthreads();
        if (it + 2 < nchunks) {
            int pst = stage + 2; if (pst >= NSTAGE) pst -= NSTAGE;
            load_chunk(sbase + (uint32_t)pst * STAGEB, (it + 2) * GBK);
        }

        const uint32_t st = sbase + (uint32_t)stage * STAGEB;
        const uint32_t aS = st + aLaneOff;
        const uint32_t bS = st + A_MATB + bTransOff;

#pragma unroll
        for (int ks = 0; ks < 4; ks++) {
            uint32_t aa[4][4], bb[8];
#pragma unroll
            for (int mi = 0; mi < 4; mi++)
                ldsm4(aa[mi], aS + mi * 16 * ROWB_A + ks * 32);
#pragma unroll
            for (int p = 0; p < 2; p++)
                ldsm4t(&bb[p * 4], bS + ks * 16 * ROWB_W + p * 32);
#pragma unroll
            for (int mi = 0; mi < 4; mi++)
#pragma unroll
                for (int nj = 0; nj < 4; nj++)
                    mma_f16(acc[mi][nj], aa[mi], &bb[nj * 2]);
        }
        if (++stage >= NSTAGE) stage = 0;
    }

    // ---- bias (per-thread columns) ----
    const int t4 = lane & 3, grp = lane >> 2;
    const int colBase = n0 + warp_n * 32 + t4 * 2;
    float bias2[4][2];
#pragma unroll
    for (int nj = 0; nj < 4; nj++) {
        const float* bp = bias + (size_t)s * D_H + colBase + nj * 8;
        bias2[nj][0] = bp[0];
        bias2[nj][1] = bp[1];
    }

    if (mode == 0) {
        const int rowBase = m0 + warp_m * 64 + grp;
#pragma unroll
        for (int mi = 0; mi < 4; mi++) {
#pragma unroll
            for (int h = 0; h < 2; h++) {
                const int row = rowBase + mi * 16 + h * 8;
                const size_t rowOff = ((size_t)s * BATCH + row) * D_H;
#pragma unroll
                for (int nj = 0; nj < 4; nj++) {
                    float v0 = fmaxf(acc[mi][nj][2 * h]     + bias2[nj][0], 0.0f);
                    float v1 = fmaxf(acc[mi][nj][2 * h + 1] + bias2[nj][1], 0.0f);
                    __half2 hv = __floats2half2_rn(v0, v1);
                    *(__half2*)(Ch + rowOff + colBase + nj * 8) = hv;
                }
            }
        }
        return;
    }

    // ---- mode 1: fused final layer ----
    __syncthreads();   // all warps past mainloop smem reads; reuse dynsmem
    __half* sWl  = (__half*)dynsmem;               // [128][16]
    float* sPart = (float*)(dynsmem + 4096);       // [4][256][16]

    // load wl slice transposed to [col 0..127][o 0..15], pad o>=10 with 0
    for (int i = tid; i < 128 * 16; i += 512) {
        int col = i >> 4, o = i & 15;
        sWl[i] = (o < D_OUT)
            ? __float2half(wls[((size_t)s * D_H + n0 + col) * D_OUT + o])
            : __float2half(0.0f);
    }
    __syncthreads();

    // B fragments for wl: local k = warp_n*32 + kc*16; n = nf*8 + grp
    uint32_t bf[2][2][2];
#pragma unroll
    for (int kc = 0; kc < 2; kc++) {
#pragma unroll
        for (int nf = 0; nf < 2; nf++) {
            int kb = warp_n * 32 + kc * 16;
            int nn = nf * 8 + grp;
            bf[kc][nf][0] = pack_h2(__half2float(sWl[(kb + t4 * 2)     * 16 + nn]),
                                    __half2float(sWl[(kb + t4 * 2 + 1) * 16 + nn]));
            bf[kc][nf][1] = pack_h2(__half2float(sWl[(kb + t4 * 2 + 8) * 16 + nn]),
                                    __half2float(sWl[(kb + t4 * 2 + 9) * 16 + nn]));
        }
    }

    // C->A frag conversion + MMA: oAcc[mi][nf][4] = v(64x32 strip) @ wl
    float oAcc[4][2][4];
#pragma unroll
    for (int mi = 0; mi < 4; mi++)
#pragma unroll
        for (int nf = 0; nf < 2; nf++)
#pragma unroll
            for (int q = 0; q < 4; q++) oAcc[mi][nf][q] = 0.0f;

#pragma unroll
    for (int mi = 0; mi < 4; mi++) {
#pragma unroll
        for (int kc = 0; kc < 2; kc++) {
            const int nj0 = 2 * kc, nj1 = 2 * kc + 1;
            uint32_t af[4];
            af[0] = pack_h2(fmaxf(acc[mi][nj0][0] + bias2[nj0][0], 0.0f),
                            fmaxf(acc[mi][nj0][1] + bias2[nj0][1], 0.0f));
            af[1] = pack_h2(fmaxf(acc[mi][nj0][2] + bias2[nj0][0], 0.0f),
                            fmaxf(acc[mi][nj0][3] + bias2[nj0][1], 0.0f));
            af[2] = pack_h2(fmaxf(acc[mi][nj1][0] + bias2[nj1][0], 0.0f),
                            fmaxf(acc[mi][nj1][1] + bias2[nj1][1], 0.0f));
            af[3] = pack_h2(fmaxf(acc[mi][nj1][2] + bias2[nj1][0], 0.0f),
                            fmaxf(acc[mi][nj1][3] + bias2[nj1][1], 0.0f));
#pragma unroll
            for (int nf = 0; nf < 2; nf++)
                mma_f16(oAcc[mi][nf], af, bf[kc][nf]);
        }
    }

    // write warp partials to smem (plain stores, deterministic)
#pragma unroll
    for (int mi = 0; mi < 4; mi++) {
#pragma unroll
        for (int nf = 0; nf < 2; nf++) {
#pragma unroll
            for (int q = 0; q < 4; q++) {
                int row = warp_m * 64 + grp + mi * 16 + ((q >> 1) ? 8 : 0);
                int oo  = nf * 8 + t4 * 2 + (q & 1);
                sPart[((size_t)warp_n * 256 + row) * 16 + oo] = oAcc[mi][nf][q];
            }
        }
    }
    __syncthreads();

    // combine 4 warp_n planes, write gmem partial slice
    for (int i = tid; i < 256 * D_OUT; i += 512) {
        int row = i / D_OUT, o = i % D_OUT;
        float sum = sPart[(size_t)(0 * 256 + row) * 16 + o]
                  + sPart[(size_t)(1 * 256 + row) * 16 + o]
                  + sPart[(size_t)(2 * 256 + row) * 16 + o]
                  + sPart[(size_t)(3 * 256 + row) * 16 + o];
        Pout[(((size_t)blockIdx.x * S_SAMP + s) * BATCH + m0 + row) * D_OUT + o] = sum;
    }
}

// ---------------------------------------------------------------------------
// kernel_launch
// ---------------------------------------------------------------------------
extern "C" void kernel_launch(void* const* d_in, const int* in_sizes, int n_in,
                              void* d_out, int out_size) {
    const float* x   = (const float*)d_in[0];
    const float* wm0 = (const float*)d_in[1];
    const float* wv0 = (const float*)d_in[2];
    const float* bm0 = (const float*)d_in[3];
    const float* bv0 = (const float*)d_in[4];
    const float* wm1 = (const float*)d_in[5];
    const float* wv1 = (const float*)d_in[6];
    const float* bm1 = (const float*)d_in[7];
    const float* bv1 = (const float*)d_in[8];
    const float* wlm = (const float*)d_in[9];
    const float* wlv = (const float*)d_in[10];
    const float* blm = (const float*)d_in[11];
    const float* blv = (const float*)d_in[12];
    const float* we0 = (const float*)d_in[13];
    const float* be0 = (const float*)d_in[14];
    const float* we1 = (const float*)d_in[15];
    const float* be1 = (const float*)d_in[16];
    const float* wel = (const float*)d_in[17];
    const float* bel = (const float*)d_in[18];
    float* out = (float*)d_out;

    __half *x16, *w016, *w116, *a016, *sig016, *sig116, *wm016, *wm116;
    float *b0, *b1, *wl, *bl, *part;
    cudaGetSymbolAddress((void**)&x16,    g_x16);
    cudaGetSymbolAddress((void**)&w016,   g_w016);
    cudaGetSymbolAddress((void**)&w116,   g_w116);
    cudaGetSymbolAddress((void**)&a016,   g_a016);
    cudaGetSymbolAddress((void**)&sig016, g_sig016);
    cudaGetSymbolAddress((void**)&sig116, g_sig116);
    cudaGetSymbolAddress((void**)&wm016,  g_wm016);
    cudaGetSymbolAddress((void**)&wm116,  g_wm116);
    cudaGetSymbolAddress((void**)&b0,     g_b0);
    cudaGetSymbolAddress((void**)&b1,     g_b1);
    cudaGetSymbolAddress((void**)&wl,     g_wl);
    cudaGetSymbolAddress((void**)&bl,     g_bl);
    cudaGetSymbolAddress((void**)&part,   g_part);

    static bool init_done = false;
    static cudaStream_t strm2 = nullptr;
    static cudaEvent_t evFork = nullptr, evJoin = nullptr, evB0 = nullptr;
    if (!init_done) {
        cudaFuncSetAttribute(gemm_mma, cudaFuncAttributeMaxDynamicSharedMemorySize, SMEM_TOTAL);
        cudaStreamCreateWithFlags(&strm2, cudaStreamNonBlocking);
        cudaEventCreateWithFlags(&evFork, cudaEventDisableTiming);
        cudaEventCreateWithFlags(&evJoin, cudaEventDisableTiming);
        cudaEventCreateWithFlags(&evB0,   cudaEventDisableTiming);
        init_done = true;
    }

    // ---- fork ----
    cudaEventRecord(evFork, 0);
    cudaStreamWaitEvent(strm2, evFork, 0);

    // ---- side stream: b0 first, then layer-1/last-layer preps ----
    {
        int total = S_SAMP * D_H;
        prep_sample<<<(total + 255) / 256, 256, 0, strm2>>>(be0, bv0, bm0, b0, D_H, total);
        cudaEventRecord(evB0, strm2);

        int n = D_H * D_H;
        prep_sw<<<(n + 255) / 256, 256, 0, strm2>>>(wv1, wm1, sig116, wm116, n);
        dim3 grid(D_H * D_H / (256 * 8), S_SAMP);
        prep_w<<<grid, 256, 0, strm2>>>(we1, sig116, wm116, w116, D_H, D_H);
        prep_sample<<<(total + 255) / 256, 256, 0, strm2>>>(be1, bv1, bm1, b1, D_H, total);
        total = S_SAMP * D_H * D_OUT;
        prep_sample<<<(total + 255) / 256, 256, 0, strm2>>>(wel, wlv, wlm, wl, D_H * D_OUT, total);
        total = S_SAMP * D_OUT;
        prep_sample<<<(total + 255) / 256, 256, 0, strm2>>>(bel, blv, blm, bl, D_OUT, total);
        cudaEventRecord(evJoin, strm2);
    }

    // ---- main stream: GEMM0 critical path ----
    {
        int n = D_IN * D_H;
        prep_sw<<<(n + 255) / 256, 256>>>(wv0, wm0, sig016, wm016, n);
        n = BATCH * K0PAD;
        prep_x<<<(n + 255) / 256, 256>>>(x, x16);
        dim3 gw(K0PAD * D_H / (256 * 8), S_SAMP);
        prep_w<<<gw, 256>>>(we0, sig016, wm016, w016, D_IN, K0PAD);
        cudaStreamWaitEvent(0, evB0, 0);
        dim3 grid(D_H / GBN, BATCH / GBM, S_SAMP);
        gemm_mma<<<grid, 512, SMEM_TOTAL>>>(x16, 0, K0PAD, w016, b0, a016,
                                            nullptr, nullptr, 0);
    }

    // ---- join, then layer 1 (fused final layer) + reduce ----
    cudaStreamWaitEvent(0, evJoin, 0);
    {
        dim3 grid(D_H / GBN, BATCH / GBM, S_SAMP);
        gemm_mma<<<grid, 512, SMEM_TOTAL>>>(a016, (size_t)BATCH * D_H, D_H, w116, b1,
                                            nullptr, wl, part, 1);
    }
    {
        int total = S_SAMP * BATCH * D_OUT;
        reduce_out<<<(total + 255) / 256, 256>>>(part, bl, out);
    }
}